// round 14
// baseline (speedup 1.0000x reference)
#include <cuda_runtime.h>
#include <cuda_fp16.h>
#include <cstdint>
#include <math.h>

#define B_   2
#define T_   4096
#define HID_ 2048
#define H_   16
#define D_   128
#define NC_  64      // T/CHUNK
#define CHK_ 64
#define QKVW 6144    // 3*H*D

// ---------------- scratch (static device globals; no runtime alloc) ----------------
__device__ float g_qkv[(size_t)B_ * T_ * QKVW];
__device__ float g_gate[(size_t)B_ * T_ * HID_];
__device__ float g_o[(size_t)B_ * T_ * HID_];
__device__ float g_og[(size_t)B_ * T_ * HID_];

// ================= helpers =================
__device__ __forceinline__ void mma_f16(float* d, const uint32_t* a, const uint32_t* b) {
    asm volatile(
        "mma.sync.aligned.m16n8k16.row.col.f32.f16.f16.f32 "
        "{%0,%1,%2,%3}, {%4,%5,%6,%7}, {%8,%9}, {%0,%1,%2,%3};"
        : "+f"(d[0]), "+f"(d[1]), "+f"(d[2]), "+f"(d[3])
        : "r"(a[0]), "r"(a[1]), "r"(a[2]), "r"(a[3]), "r"(b[0]), "r"(b[1]));
}
__device__ __forceinline__ void mma_tf32(float* d, const uint32_t* a, const uint32_t* b) {
    asm volatile(
        "mma.sync.aligned.m16n8k8.row.col.f32.tf32.tf32.f32 "
        "{%0,%1,%2,%3}, {%4,%5,%6,%7}, {%8,%9}, {%0,%1,%2,%3};"
        : "+f"(d[0]), "+f"(d[1]), "+f"(d[2]), "+f"(d[3])
        : "r"(a[0]), "r"(a[1]), "r"(a[2]), "r"(a[3]), "r"(b[0]), "r"(b[1]));
}
__device__ __forceinline__ uint32_t h2pack(float lo, float hi) {
    __half2 h = __floats2half2_rn(lo, hi);
    return *reinterpret_cast<uint32_t*>(&h);
}
// tf32 round-to-nearest on fp32 bit pattern
__device__ __forceinline__ float rtf(float x) {
    return __uint_as_float(__float_as_uint(x) + 0x1000u);
}
__device__ __forceinline__ uint32_t rtu(float x) {
    return __float_as_uint(x) + 0x1000u;
}

// ================= fp16 mma.sync NT GEMM: C[M,N] = A[M,K] * B[N,K]^T =================
// Block tile 128x128, BK=32, 256 threads = 8 warps (2x4), warp tile 64x32.
// fp16 in smem (half crossbar traffic), fp32 accum. Software-pipelined
// LDG -> cvt -> STS with prefetch distance 2. 2 CTAs/SM.
#define HS    40                           // halves per smem row (32 + pad)
#define HSTG  (128 * HS)                   // halves per tile (A or B)
#define GSMEM (2 * 2 * HSTG * 2)           // 2 stages * (A+B) * 2 bytes = 40960

__global__ __launch_bounds__(256, 2)
void gemm_mma(const float* __restrict__ A, const float* __restrict__ Bm,
              float* __restrict__ C, int M, int N, int K) {
    extern __shared__ __half hsm[];
    const int tid = threadIdx.x;
    const int lane = tid & 31, wid = tid >> 5;
    const int g = lane >> 2, c = lane & 3;
    const int bm = blockIdx.y * 128, bn = blockIdx.x * 128;
    const int wm = (wid >> 2) * 64, wn = (wid & 3) * 32;
    const int KIT = K >> 5;

    // loader mapping: each thread owns row = tid>>1, k-half = (tid&1)*16
    const int lrow = tid >> 1;
    const int lkh = (tid & 1) * 16;
    const float* gA = A + (size_t)(bm + lrow) * K + lkh;
    const float* gB = Bm + (size_t)(bn + lrow) * K + lkh;

    float4 fa[2], fb[2], fa2[2], fb2[2];
    uint32_t hbuf[8];   // 4 A half2 + 4 B half2

    auto ldg_stage = [&](int kt, float4* xa, float4* xb) {
        const float* pa = gA + (size_t)kt * 32;
        xa[0] = *(const float4*)(pa);
        xa[1] = *(const float4*)(pa + 4);
        xa[2] = *(const float4*)(pa + 8);
        xa[3] = *(const float4*)(pa + 12);
        const float* pb = gB + (size_t)kt * 32;
        xb[0] = *(const float4*)(pb);
        xb[1] = *(const float4*)(pb + 4);
        xb[2] = *(const float4*)(pb + 8);
        xb[3] = *(const float4*)(pb + 12);
    };
    // NOTE: xa[2],xa[3] alias into xa2 in caller; use 4-float4 form per matrix
    auto cvt_stage = [&](const float4* xa, const float4* xb, uint32_t* h) {
        h[0] = h2pack(xa[0].x, xa[0].y); h[1] = h2pack(xa[0].z, xa[0].w);
        h[2] = h2pack(xa[1].x, xa[1].y); h[3] = h2pack(xa[1].z, xa[1].w);
        h[4] = h2pack(xb[0].x, xb[0].y); h[5] = h2pack(xb[0].z, xb[0].w);
        h[6] = h2pack(xb[1].x, xb[1].y); h[7] = h2pack(xb[1].z, xb[1].w);
    };
    auto sts_stage = [&](const uint32_t* h, const uint32_t* h2, int s) {
        __half* base = hsm + s * (2 * HSTG);
        uint32_t* dA = (uint32_t*)(base + lrow * HS + lkh);
        dA[0] = h[0]; dA[1] = h[1]; dA[2] = h[2]; dA[3] = h[3];
        uint32_t* dA2 = dA + 4;
        dA2[0] = h2[0]; dA2[1] = h2[1]; dA2[2] = h2[2]; dA2[3] = h2[3];
        uint32_t* dB = (uint32_t*)(base + HSTG + lrow * HS + lkh);
        dB[0] = h[4]; dB[1] = h[5]; dB[2] = h[6]; dB[3] = h[7];
        uint32_t* dB2 = dB + 4;
        dB2[0] = h2[4]; dB2[1] = h2[5]; dB2[2] = h2[6]; dB2[3] = h2[7];
    };

    float d[4][4][4];
#pragma unroll
    for (int mt = 0; mt < 4; mt++)
#pragma unroll
        for (int nt = 0; nt < 4; nt++)
#pragma unroll
            for (int i = 0; i < 4; i++) d[mt][nt][i] = 0.f;

    uint32_t hbuf2[8];
    // prologue: stage 0 straight to smem, stage 1 held in hbuf
    ldg_stage(0, fa, fb);
    ldg_stage(0, fa2, fb2);   // placeholder overwritten below (keeps reg shape)
    {
        // full 16-float loads per matrix: first 8 in fa/fb, last 8 in fa2/fb2
        const float* pa = gA;
        fa[0] = *(const float4*)(pa);      fa[1] = *(const float4*)(pa + 4);
        fa2[0] = *(const float4*)(pa + 8); fa2[1] = *(const float4*)(pa + 12);
        const float* pb = gB;
        fb[0] = *(const float4*)(pb);      fb[1] = *(const float4*)(pb + 4);
        fb2[0] = *(const float4*)(pb + 8); fb2[1] = *(const float4*)(pb + 12);
        cvt_stage(fa, fb, hbuf);
        cvt_stage(fa2, fb2, hbuf2);
        sts_stage(hbuf, hbuf2, 0);
    }
    {
        const float* pa = gA + 32;
        fa[0] = *(const float4*)(pa);      fa[1] = *(const float4*)(pa + 4);
        fa2[0] = *(const float4*)(pa + 8); fa2[1] = *(const float4*)(pa + 12);
        const float* pb = gB + 32;
        fb[0] = *(const float4*)(pb);      fb[1] = *(const float4*)(pb + 4);
        fb2[0] = *(const float4*)(pb + 8); fb2[1] = *(const float4*)(pb + 12);
        cvt_stage(fa, fb, hbuf);
        cvt_stage(fa2, fb2, hbuf2);
    }
    __syncthreads();

    for (int it = 0; it < KIT; it++) {
        if (it + 1 < KIT) sts_stage(hbuf, hbuf2, (it + 1) & 1);
        if (it + 2 < KIT) {
            const float* pa = gA + (size_t)(it + 2) * 32;
            fa[0] = *(const float4*)(pa);      fa[1] = *(const float4*)(pa + 4);
            fa2[0] = *(const float4*)(pa + 8); fa2[1] = *(const float4*)(pa + 12);
            const float* pb = gB + (size_t)(it + 2) * 32;
            fb[0] = *(const float4*)(pb);      fb[1] = *(const float4*)(pb + 4);
            fb2[0] = *(const float4*)(pb + 8); fb2[1] = *(const float4*)(pb + 12);
        }

        const __half* As = hsm + (it & 1) * (2 * HSTG);
        const __half* Bs = As + HSTG;
#pragma unroll
        for (int ks = 0; ks < 2; ks++) {
            const int kb = ks * 16;
            uint32_t a[4][4];
#pragma unroll
            for (int mt = 0; mt < 4; mt++) {
                const __half* p = As + (wm + mt * 16 + g) * HS + kb + 2 * c;
                a[mt][0] = *(const uint32_t*)(p);
                a[mt][1] = *(const uint32_t*)(p + 8 * HS);
                a[mt][2] = *(const uint32_t*)(p + 8);
                a[mt][3] = *(const uint32_t*)(p + 8 * HS + 8);
            }
            uint32_t b[4][2];
#pragma unroll
            for (int nt = 0; nt < 4; nt++) {
                const __half* q = Bs + (wn + nt * 8 + g) * HS + kb + 2 * c;
                b[nt][0] = *(const uint32_t*)(q);
                b[nt][1] = *(const uint32_t*)(q + 8);
            }
#pragma unroll
            for (int mt = 0; mt < 4; mt++)
#pragma unroll
                for (int nt = 0; nt < 4; nt++)
                    mma_f16(d[mt][nt], a[mt], b[nt]);
        }

        if (it + 2 < KIT) {
            cvt_stage(fa, fb, hbuf);
            cvt_stage(fa2, fb2, hbuf2);
        }
        __syncthreads();
    }

#pragma unroll
    for (int mt = 0; mt < 4; mt++) {
        const int r0 = bm + wm + mt * 16 + g;
#pragma unroll
        for (int nt = 0; nt < 4; nt++) {
            const int c0 = bn + wn + nt * 8 + 2 * c;
            *(float2*)&C[(size_t)r0 * N + c0]       = make_float2(d[mt][nt][0], d[mt][nt][1]);
            *(float2*)&C[(size_t)(r0 + 8) * N + c0] = make_float2(d[mt][nt][2], d[mt][nt][3]);
        }
    }
}

// ---------------- q/k rmsnorm + RoPE (+ q * D^-0.5), in place on g_qkv ----------------
__global__ __launch_bounds__(256)
void prep_qk(float* __restrict__ qkv, const float* __restrict__ qw,
             const float* __restrict__ kw, const int* __restrict__ pos_ids) {
    const int bt = blockIdx.x;
    const int lane = threadIdx.x & 31;
    const int warp = threadIdx.x >> 5;
    const float pos = (float)pos_ids[bt];
    const float invf = expf(-(float)lane * (logf(10000.0f) / 32.0f));
    const float fr = pos * invf;
    const float cs = cosf(fr), sn = sinf(fr);

    for (int r = warp; r < 32; r += 8) {
        const int hh = r >> 1;
        const int isK = r & 1;
        float* row = qkv + (size_t)bt * QKVW + isK * (H_ * D_) + hh * D_;
        const float* w = isK ? kw : qw;
        float v0 = row[lane], v1 = row[lane + 32], v2 = row[lane + 64], v3 = row[lane + 96];
        float ss = v0 * v0 + v1 * v1 + v2 * v2 + v3 * v3;
#pragma unroll
        for (int o = 16; o; o >>= 1) ss += __shfl_xor_sync(0xFFFFFFFFu, ss, o);
        const float rs = rsqrtf(ss * (1.f / 128.f) + 1e-6f);
        v0 = v0 * rs * w[lane];      v1 = v1 * rs * w[lane + 32];
        v2 = v2 * rs * w[lane + 64]; v3 = v3 * rs * w[lane + 96];
        float nv0 = v0 * cs - v1 * sn;
        float nv1 = v1 * cs + v0 * sn;
        v0 = nv0; v1 = nv1;
        if (!isK) {
            const float sc = 0.08838834764831845f;
            v0 *= sc; v1 *= sc; v2 *= sc; v3 *= sc;
        }
        row[lane] = v0; row[lane + 32] = v1; row[lane + 64] = v2; row[lane + 96] = v3;
    }
}

// ================= chunked GLA, tf32 mma.sync, 256 threads (R6-proven) =================
#define QS 132   // sQ/sK row stride (floats)
#define VS 36    // sV/sS row stride
#define AS 68    // sAtt row stride
#define GLA_SMEM_FLOATS (64*QS + 64*QS + 64*VS + 128*VS + 64*AS + 80)

__global__ __launch_bounds__(256, 1)
void gla_kernel(const float* __restrict__ qkv, float* __restrict__ o_out) {
    extern __shared__ float sm[];
    float* sQ   = sm;                  // [64][QS]
    float* sK   = sQ + 64 * QS;        // [64][QS]
    float* sV   = sK + 64 * QS;        // [64][VS]
    float* sS   = sV + 64 * VS;        // [128][VS]
    float* sAtt = sS + 128 * VS;       // [64][AS]
    float* expg = sAtt + 64 * AS;      // [80]

    const int tid = threadIdx.x;
    const int lane = tid & 31, w = tid >> 5;
    const int g = lane >> 2, c = lane & 3;
    const int gs = blockIdx.x;
    const int h  = blockIdx.y;
    const int b  = blockIdx.z;

    float gg;
    {
        const double scale = 1.0 - 11.0 / 31.0 + 1e-5;
        const double sl = pow(2.0, -0.5 * (double)(h + 1));
        gg = (float)(-sl * scale);
    }
    if (tid <= 64) expg[tid] = expf(gg * (float)tid);
    for (int i = tid; i < 128 * VS; i += 256) sS[i] = 0.f;

    float fs[4][4];
#pragma unroll
    for (int nt = 0; nt < 4; nt++)
#pragma unroll
        for (int i = 0; i < 4; i++) fs[nt][i] = 0.f;

    __syncthreads();
    const float chdec = expg[64];

    const float* qb = qkv + (size_t)b * T_ * QKVW + h * D_;
    const int dvb = gs * 32;

    const int a_mq = (w >> 1) * 16;
    const int a_ne = (w & 1) * 32;
    const int o_mo = (w >> 1) * 16;
    const int o_no = (w & 1) * 16;
    const int s_m0 = w * 16;

    for (int ck = 0; ck < NC_; ck++) {
        const float* crow = qb + (size_t)ck * CHK_ * QKVW;
        for (int f = tid; f < 64 * 32; f += 256) {
            int r = f >> 5;
            int d4 = (f & 31) << 2;
            float4 qv = *(const float4*)(crow + (size_t)r * QKVW + d4);
            sQ[r * QS + d4 + 0] = rtf(qv.x); sQ[r * QS + d4 + 1] = rtf(qv.y);
            sQ[r * QS + d4 + 2] = rtf(qv.z); sQ[r * QS + d4 + 3] = rtf(qv.w);
            float4 kv = *(const float4*)(crow + (size_t)r * QKVW + 2048 + d4);
            sK[r * QS + d4 + 0] = rtf(kv.x); sK[r * QS + d4 + 1] = rtf(kv.y);
            sK[r * QS + d4 + 2] = rtf(kv.z); sK[r * QS + d4 + 3] = rtf(kv.w);
        }
        for (int f = tid; f < 64 * 8; f += 256) {
            int r = f >> 3;
            int d4 = (f & 7) << 2;
            float4 vv = *(const float4*)(crow + (size_t)r * QKVW + 4096 + dvb + d4);
            sV[r * VS + d4 + 0] = rtf(vv.x); sV[r * VS + d4 + 1] = rtf(vv.y);
            sV[r * VS + d4 + 2] = rtf(vv.z); sV[r * VS + d4 + 3] = rtf(vv.w);
        }
        __syncthreads();

        // ---- att = Q @ K^T (64x64, k=128), mask+decay -> sAtt (rounded) ----
        {
            float fa[4][4];
#pragma unroll
            for (int nt = 0; nt < 4; nt++)
#pragma unroll
                for (int i = 0; i < 4; i++) fa[nt][i] = 0.f;
#pragma unroll
            for (int k0 = 0; k0 < 16; k0++) {
                uint32_t a[4];
                const float* pa = sQ + (a_mq + g) * QS + k0 * 8 + c;
                a[0] = __float_as_uint(pa[0]);
                a[1] = __float_as_uint(pa[8 * QS]);
                a[2] = __float_as_uint(pa[4]);
                a[3] = __float_as_uint(pa[8 * QS + 4]);
#pragma unroll
                for (int nt = 0; nt < 4; nt++) {
                    uint32_t bb[2];
                    const float* pb = sK + (a_ne + nt * 8 + g) * QS + k0 * 8 + c;
                    bb[0] = __float_as_uint(pb[0]);
                    bb[1] = __float_as_uint(pb[4]);
                    mma_tf32(fa[nt], a, bb);
                }
            }
#pragma unroll
            for (int nt = 0; nt < 4; nt++) {
                const int e0 = a_ne + nt * 8 + 2 * c;
                const int r0 = a_mq + g, r1 = a_mq + g + 8;
                float v;
                v = (r0 >= e0)     ? fa[nt][0] * expg[r0 - e0]     : 0.f;
                sAtt[r0 * AS + e0]     = rtf(v);
                v = (r0 >= e0 + 1) ? fa[nt][1] * expg[r0 - e0 - 1] : 0.f;
                sAtt[r0 * AS + e0 + 1] = rtf(v);
                v = (r1 >= e0)     ? fa[nt][2] * expg[r1 - e0]     : 0.f;
                sAtt[r1 * AS + e0]     = rtf(v);
                v = (r1 >= e0 + 1) ? fa[nt][3] * expg[r1 - e0 - 1] : 0.f;
                sAtt[r1 * AS + e0 + 1] = rtf(v);
            }
        }
        __syncthreads();

        // ---- o = att @ V + qdec * (Q @ S_prev)  (64x32) -> gmem ----
        {
            float fi[2][4], fr[2][4];
#pragma unroll
            for (int nt = 0; nt < 2; nt++)
#pragma unroll
                for (int i = 0; i < 4; i++) { fi[nt][i] = 0.f; fr[nt][i] = 0.f; }
#pragma unroll
            for (int k0 = 0; k0 < 8; k0++) {          // intra, k over e
                uint32_t a[4];
                const float* pa = sAtt + (o_mo + g) * AS + k0 * 8 + c;
                a[0] = __float_as_uint(pa[0]);
                a[1] = __float_as_uint(pa[8 * AS]);
                a[2] = __float_as_uint(pa[4]);
                a[3] = __float_as_uint(pa[8 * AS + 4]);
#pragma unroll
                for (int nt = 0; nt < 2; nt++) {
                    uint32_t bb[2];
                    bb[0] = __float_as_uint(sV[(k0 * 8 + c) * VS + o_no + nt * 8 + g]);
                    bb[1] = __float_as_uint(sV[(k0 * 8 + c + 4) * VS + o_no + nt * 8 + g]);
                    mma_tf32(fi[nt], a, bb);
                }
            }
#pragma unroll
            for (int k0 = 0; k0 < 16; k0++) {         // inter, k over d
                uint32_t a[4];
                const float* pa = sQ + (o_mo + g) * QS + k0 * 8 + c;
                a[0] = __float_as_uint(pa[0]);
                a[1] = __float_as_uint(pa[8 * QS]);
                a[2] = __float_as_uint(pa[4]);
                a[3] = __float_as_uint(pa[8 * QS + 4]);
#pragma unroll
                for (int nt = 0; nt < 2; nt++) {
                    uint32_t bb[2];
                    bb[0] = __float_as_uint(sS[(k0 * 8 + c) * VS + o_no + nt * 8 + g]);
                    bb[1] = __float_as_uint(sS[(k0 * 8 + c + 4) * VS + o_no + nt * 8 + g]);
                    mma_tf32(fr[nt], a, bb);
                }
            }
            const int r0 = o_mo + g, r1 = o_mo + g + 8;
            const float qd0 = expg[r0 + 1], qd1 = expg[r1 + 1];
            const size_t obase = ((size_t)b * T_ + (size_t)ck * CHK_) * HID_ + h * D_ + dvb;
#pragma unroll
            for (int nt = 0; nt < 2; nt++) {
                const int col = o_no + nt * 8 + 2 * c;
                *(float2*)(o_out + obase + (size_t)r0 * HID_ + col) =
                    make_float2(fi[nt][0] + qd0 * fr[nt][0], fi[nt][1] + qd0 * fr[nt][1]);
                *(float2*)(o_out + obase + (size_t)r1 * HID_ + col) =
                    make_float2(fi[nt][2] + qd1 * fr[nt][2], fi[nt][3] + qd1 * fr[nt][3]);
            }
        }

        // ---- state: fs = chdec*fs + (kdec*K)^T @ V   (128x32, k=64) ----
        {
#pragma unroll
            for (int nt = 0; nt < 4; nt++)
#pragma unroll
                for (int i = 0; i < 4; i++) fs[nt][i] *= chdec;
#pragma unroll
            for (int k0 = 0; k0 < 8; k0++) {
                const float kd0 = expg[63 - (k0 * 8 + c)];
                const float kd1 = expg[63 - (k0 * 8 + c + 4)];
                uint32_t a[4];
                a[0] = rtu(sK[(k0 * 8 + c) * QS + s_m0 + g] * kd0);
                a[1] = rtu(sK[(k0 * 8 + c) * QS + s_m0 + g + 8] * kd0);
                a[2] = rtu(sK[(k0 * 8 + c + 4) * QS + s_m0 + g] * kd1);
                a[3] = rtu(sK[(k0 * 8 + c + 4) * QS + s_m0 + g + 8] * kd1);
#pragma unroll
                for (int nt = 0; nt < 4; nt++) {
                    uint32_t bb[2];
                    bb[0] = __float_as_uint(sV[(k0 * 8 + c) * VS + nt * 8 + g]);
                    bb[1] = __float_as_uint(sV[(k0 * 8 + c + 4) * VS + nt * 8 + g]);
                    mma_tf32(fs[nt], a, bb);
                }
            }
        }
        __syncthreads();

        // mirror state frags to sS (tf32-rounded) for next chunk's q@S
        {
            const int r0 = s_m0 + g, r1 = s_m0 + g + 8;
#pragma unroll
            for (int nt = 0; nt < 4; nt++) {
                const int col = nt * 8 + 2 * c;
                sS[r0 * VS + col]     = rtf(fs[nt][0]);
                sS[r0 * VS + col + 1] = rtf(fs[nt][1]);
                sS[r1 * VS + col]     = rtf(fs[nt][2]);
                sS[r1 * VS + col + 1] = rtf(fs[nt][3]);
            }
        }
    }
}

// ---------------- group rmsnorm * sigmoid(gate) ----------------
__global__ __launch_bounds__(256)
void epilogue_k(const float* __restrict__ o_in, const float* __restrict__ gate,
                const float* __restrict__ gw, float* __restrict__ og) {
    const int bt = blockIdx.x;
    const int lane = threadIdx.x & 31;
    const int warp = threadIdx.x >> 5;
    for (int hh = warp; hh < H_; hh += 8) {
        const size_t base = (size_t)bt * HID_ + hh * D_;
        const float* row = o_in + base;
        float v0 = row[lane], v1 = row[lane + 32], v2 = row[lane + 64], v3 = row[lane + 96];
        float ss = v0 * v0 + v1 * v1 + v2 * v2 + v3 * v3;
#pragma unroll
        for (int o = 16; o; o >>= 1) ss += __shfl_xor_sync(0xFFFFFFFFu, ss, o);
        const float rs = rsqrtf(ss * (1.f / 128.f) + 1e-6f);
        const float* gr = gate + base;
        float* out = og + base;
#pragma unroll
        for (int i = 0; i < 4; i++) {
            const int d = lane + 32 * i;
            float v = (i == 0) ? v0 : (i == 1) ? v1 : (i == 2) ? v2 : v3;
            float sg = 1.f / (1.f + expf(-gr[d]));
            out[d] = v * rs * gw[hh * D_ + d] * sg;
        }
    }
}

// ---------------- launch ----------------
extern "C" void kernel_launch(void* const* d_in, const int* in_sizes, int n_in,
                              void* d_out, int out_size) {
    const float* hidden   = (const float*)d_in[0];
    const float* w_qkv    = (const float*)d_in[1];
    const float* q_ln_w   = (const float*)d_in[2];
    const float* k_ln_w   = (const float*)d_in[3];
    const float* g_norm_w = (const float*)d_in[4];
    const float* w_g_proj = (const float*)d_in[5];
    const float* w_dense  = (const float*)d_in[6];
    const int*   pos_ids  = (const int*)d_in[7];
    float* out = (float*)d_out;

    float *qkv_p, *gate_p, *o_p, *og_p;
    cudaGetSymbolAddress((void**)&qkv_p, g_qkv);
    cudaGetSymbolAddress((void**)&gate_p, g_gate);
    cudaGetSymbolAddress((void**)&o_p, g_o);
    cudaGetSymbolAddress((void**)&og_p, g_og);

    const int M = B_ * T_;
    cudaFuncSetAttribute(gla_kernel, cudaFuncAttributeMaxDynamicSharedMemorySize,
                         GLA_SMEM_FLOATS * (int)sizeof(float));
    cudaFuncSetAttribute(gemm_mma, cudaFuncAttributeMaxDynamicSharedMemorySize, GSMEM);

    // 1) qkv projection (fp16 mma.sync m16n8k16)
    gemm_mma<<<dim3(QKVW / 128, M / 128), 256, GSMEM>>>(hidden, w_qkv, qkv_p, M, QKVW, HID_);
    // 2) gate projection
    gemm_mma<<<dim3(HID_ / 128, M / 128), 256, GSMEM>>>(hidden, w_g_proj, gate_p, M, HID_, HID_);
    // 3) rmsnorm + rope on q,k
    prep_qk<<<M, 256>>>(qkv_p, q_ln_w, k_ln_w, pos_ids);
    // 4) chunked gated linear attention (tf32, R6-proven 256 threads)
    gla_kernel<<<dim3(4, H_, B_), 256, GLA_SMEM_FLOATS * sizeof(float)>>>(qkv_p, o_p);
    // 5) group rmsnorm * sigmoid gate
    epilogue_k<<<M, 256>>>(o_p, gate_p, g_norm_w, og_p);
    // 6) dense output projection
    gemm_mma<<<dim3(HID_ / 128, M / 128), 256, GSMEM>>>(og_p, w_dense, out, M, HID_, HID_);
}

// round 15
// speedup vs baseline: 1.8957x; 1.8957x over previous
#include <cuda_runtime.h>
#include <cuda_fp16.h>
#include <cstdint>
#include <math.h>

#define B_   2
#define T_   4096
#define HID_ 2048
#define H_   16
#define D_   128
#define NC_  64      // T/CHUNK
#define CHK_ 64
#define QKVW 6144    // 3*H*D

// ---------------- scratch (static device globals; no runtime alloc) ----------------
__device__ float  g_qkv[(size_t)B_ * T_ * QKVW];
__device__ float  g_gate[(size_t)B_ * T_ * HID_];
__device__ float  g_o[(size_t)B_ * T_ * HID_];
__device__ __half g_og_h[(size_t)B_ * T_ * HID_];     // gated output, fp16 (GEMM3 A)
__device__ __half g_hid_h[(size_t)B_ * T_ * HID_];    // fp16 hidden
__device__ __half g_wqkv_h[(size_t)QKVW * HID_];      // fp16 weights
__device__ __half g_wg_h[(size_t)HID_ * HID_];
__device__ __half g_wd_h[(size_t)HID_ * HID_];

// ================= helpers =================
__device__ __forceinline__ uint32_t smem_u32(const void* p) {
    uint32_t a;
    asm("{ .reg .u64 t; cvta.to.shared.u64 t, %1; cvt.u32.u64 %0, t; }" : "=r"(a) : "l"(p));
    return a;
}
#define CP_ASYNC16(dst, src) \
    asm volatile("cp.async.cg.shared.global [%0], [%1], 16;" \
                 :: "r"(dst), "l"(__cvta_generic_to_global(src)))
#define CP_COMMIT() asm volatile("cp.async.commit_group;" ::: "memory")
#define CP_WAIT1()  asm volatile("cp.async.wait_group 1;" ::: "memory")

__device__ __forceinline__ void mma_f16(float* d, const uint32_t* a, const uint32_t* b) {
    asm volatile(
        "mma.sync.aligned.m16n8k16.row.col.f32.f16.f16.f32 "
        "{%0,%1,%2,%3}, {%4,%5,%6,%7}, {%8,%9}, {%0,%1,%2,%3};"
        : "+f"(d[0]), "+f"(d[1]), "+f"(d[2]), "+f"(d[3])
        : "r"(a[0]), "r"(a[1]), "r"(a[2]), "r"(a[3]), "r"(b[0]), "r"(b[1]));
}
__device__ __forceinline__ void mma_tf32(float* d, const uint32_t* a, const uint32_t* b) {
    asm volatile(
        "mma.sync.aligned.m16n8k8.row.col.f32.tf32.tf32.f32 "
        "{%0,%1,%2,%3}, {%4,%5,%6,%7}, {%8,%9}, {%0,%1,%2,%3};"
        : "+f"(d[0]), "+f"(d[1]), "+f"(d[2]), "+f"(d[3])
        : "r"(a[0]), "r"(a[1]), "r"(a[2]), "r"(a[3]), "r"(b[0]), "r"(b[1]));
}
__device__ __forceinline__ uint32_t h2pack(float lo, float hi) {
    __half2 h = __floats2half2_rn(lo, hi);
    return *reinterpret_cast<uint32_t*>(&h);
}
// tf32 round-to-nearest on fp32 bit pattern
__device__ __forceinline__ float rtf(float x) {
    return __uint_as_float(__float_as_uint(x) + 0x1000u);
}
__device__ __forceinline__ uint32_t rtu(float x) {
    return __float_as_uint(x) + 0x1000u;
}

// ---------------- fp32 -> fp16 bulk convert ----------------
__global__ __launch_bounds__(256)
void cvt_f2h(const float4* __restrict__ in, uint2* __restrict__ out, int n4) {
    int i = blockIdx.x * blockDim.x + threadIdx.x;
    if (i < n4) {
        float4 v = in[i];
        uint2 o;
        o.x = h2pack(v.x, v.y);
        o.y = h2pack(v.z, v.w);
        out[i] = o;
    }
}

// ================= fp16 mma.sync NT GEMM: C[M,N] = A[M,K] * B[N,K]^T =================
// Exact R6 skeleton on fp16 operands: block tile 128x128, BK=32, 256 threads =
// 8 warps (2x4), warp tile 64x32 of m16n8k16, 2-stage cp.async load-before-wait,
// scalar LDS.32 fragment loads, 2 CTAs/SM.
#define HS    40                            // halves per smem row (32 + 8 pad)
#define HSTGH (256 * HS)                    // halves per stage (A 128 rows + B 128 rows)
#define GSMEM (2 * HSTGH * 2)               // bytes: 2 stages * stage * 2B = 40960

__global__ __launch_bounds__(256, 2)
void gemm_mma(const __half* __restrict__ A, const __half* __restrict__ Bm,
              float* __restrict__ C, int M, int N, int K) {
    extern __shared__ __half hsm[];
    const uint32_t sb = smem_u32(hsm);
    const int tid = threadIdx.x;
    const int lane = tid & 31, wid = tid >> 5;
    const int g = lane >> 2, c = lane & 3;
    const int bm = blockIdx.y * 128, bn = blockIdx.x * 128;
    const int wm = (wid >> 2) * 64, wn = (wid & 3) * 32;
    const int KIT = K >> 5;

    auto load_stage = [&](int s, int kt) {
        const uint32_t ab = sb + (uint32_t)s * (HSTGH * 2);
        const uint32_t bb = ab + 128 * HS * 2;
        const size_t kofs = (size_t)kt * 32;
#pragma unroll
        for (int i = 0; i < 2; i++) {              // A: 128 rows x 4 chunks of 8 halves
            int id = tid + i * 256;
            int row = id >> 2, c4 = id & 3;
            CP_ASYNC16(ab + (uint32_t)(row * (HS * 2) + c4 * 16),
                       A + (size_t)(bm + row) * K + kofs + c4 * 8);
        }
#pragma unroll
        for (int i = 0; i < 2; i++) {              // B: 128 rows x 4 chunks
            int id = tid + i * 256;
            int row = id >> 2, c4 = id & 3;
            CP_ASYNC16(bb + (uint32_t)(row * (HS * 2) + c4 * 16),
                       Bm + (size_t)(bn + row) * K + kofs + c4 * 8);
        }
    };

    float d[4][4][4];
#pragma unroll
    for (int mt = 0; mt < 4; mt++)
#pragma unroll
        for (int nt = 0; nt < 4; nt++)
#pragma unroll
            for (int i = 0; i < 4; i++) d[mt][nt][i] = 0.f;

    load_stage(0, 0);
    CP_COMMIT();

    for (int it = 0; it < KIT; it++) {
        if (it + 1 < KIT) load_stage((it + 1) & 1, it + 1);
        CP_COMMIT();
        CP_WAIT1();
        __syncthreads();

        const __half* As = hsm + (it & 1) * HSTGH;
        const __half* Bs = As + 128 * HS;
#pragma unroll
        for (int ks = 0; ks < 2; ks++) {
            const int kb = ks * 16;
            uint32_t a[4][4];
#pragma unroll
            for (int mt = 0; mt < 4; mt++) {
                const __half* p = As + (wm + mt * 16 + g) * HS + kb + 2 * c;
                a[mt][0] = *(const uint32_t*)(p);
                a[mt][1] = *(const uint32_t*)(p + 8 * HS);
                a[mt][2] = *(const uint32_t*)(p + 8);
                a[mt][3] = *(const uint32_t*)(p + 8 * HS + 8);
            }
            uint32_t b[4][2];
#pragma unroll
            for (int nt = 0; nt < 4; nt++) {
                const __half* q = Bs + (wn + nt * 8 + g) * HS + kb + 2 * c;
                b[nt][0] = *(const uint32_t*)(q);
                b[nt][1] = *(const uint32_t*)(q + 8);
            }
#pragma unroll
            for (int mt = 0; mt < 4; mt++)
#pragma unroll
                for (int nt = 0; nt < 4; nt++)
                    mma_f16(d[mt][nt], a[mt], b[nt]);
        }
        __syncthreads();
    }

#pragma unroll
    for (int mt = 0; mt < 4; mt++) {
        const int r0 = bm + wm + mt * 16 + g;
#pragma unroll
        for (int nt = 0; nt < 4; nt++) {
            const int c0 = bn + wn + nt * 8 + 2 * c;
            *(float2*)&C[(size_t)r0 * N + c0]       = make_float2(d[mt][nt][0], d[mt][nt][1]);
            *(float2*)&C[(size_t)(r0 + 8) * N + c0] = make_float2(d[mt][nt][2], d[mt][nt][3]);
        }
    }
}

// ---------------- q/k rmsnorm + RoPE (+ q * D^-0.5), in place on g_qkv ----------------
__global__ __launch_bounds__(256)
void prep_qk(float* __restrict__ qkv, const float* __restrict__ qw,
             const float* __restrict__ kw, const int* __restrict__ pos_ids) {
    const int bt = blockIdx.x;
    const int lane = threadIdx.x & 31;
    const int warp = threadIdx.x >> 5;
    const float pos = (float)pos_ids[bt];
    const float invf = expf(-(float)lane * (logf(10000.0f) / 32.0f));
    const float fr = pos * invf;
    const float cs = cosf(fr), sn = sinf(fr);

    for (int r = warp; r < 32; r += 8) {
        const int hh = r >> 1;
        const int isK = r & 1;
        float* row = qkv + (size_t)bt * QKVW + isK * (H_ * D_) + hh * D_;
        const float* w = isK ? kw : qw;
        float v0 = row[lane], v1 = row[lane + 32], v2 = row[lane + 64], v3 = row[lane + 96];
        float ss = v0 * v0 + v1 * v1 + v2 * v2 + v3 * v3;
#pragma unroll
        for (int o = 16; o; o >>= 1) ss += __shfl_xor_sync(0xFFFFFFFFu, ss, o);
        const float rs = rsqrtf(ss * (1.f / 128.f) + 1e-6f);
        v0 = v0 * rs * w[lane];      v1 = v1 * rs * w[lane + 32];
        v2 = v2 * rs * w[lane + 64]; v3 = v3 * rs * w[lane + 96];
        float nv0 = v0 * cs - v1 * sn;
        float nv1 = v1 * cs + v0 * sn;
        v0 = nv0; v1 = nv1;
        if (!isK) {
            const float sc = 0.08838834764831845f;
            v0 *= sc; v1 *= sc; v2 *= sc; v3 *= sc;
        }
        row[lane] = v0; row[lane + 32] = v1; row[lane + 64] = v2; row[lane + 96] = v3;
    }
}

// ================= chunked GLA, tf32 mma.sync, 256 threads (R6-proven) =================
#define QS 132   // sQ/sK row stride (floats)
#define VS 36    // sV/sS row stride
#define AS 68    // sAtt row stride
#define GLA_SMEM_FLOATS (64*QS + 64*QS + 64*VS + 128*VS + 64*AS + 80)

__global__ __launch_bounds__(256, 1)
void gla_kernel(const float* __restrict__ qkv, float* __restrict__ o_out) {
    extern __shared__ float sm[];
    float* sQ   = sm;                  // [64][QS]
    float* sK   = sQ + 64 * QS;        // [64][QS]
    float* sV   = sK + 64 * QS;        // [64][VS]
    float* sS   = sV + 64 * VS;        // [128][VS]
    float* sAtt = sS + 128 * VS;       // [64][AS]
    float* expg = sAtt + 64 * AS;      // [80]

    const int tid = threadIdx.x;
    const int lane = tid & 31, w = tid >> 5;
    const int g = lane >> 2, c = lane & 3;
    const int gs = blockIdx.x;
    const int h  = blockIdx.y;
    const int b  = blockIdx.z;

    float gg;
    {
        const double scale = 1.0 - 11.0 / 31.0 + 1e-5;
        const double sl = pow(2.0, -0.5 * (double)(h + 1));
        gg = (float)(-sl * scale);
    }
    if (tid <= 64) expg[tid] = expf(gg * (float)tid);
    for (int i = tid; i < 128 * VS; i += 256) sS[i] = 0.f;

    float fs[4][4];
#pragma unroll
    for (int nt = 0; nt < 4; nt++)
#pragma unroll
        for (int i = 0; i < 4; i++) fs[nt][i] = 0.f;

    __syncthreads();
    const float chdec = expg[64];

    const float* qb = qkv + (size_t)b * T_ * QKVW + h * D_;
    const int dvb = gs * 32;

    const int a_mq = (w >> 1) * 16;
    const int a_ne = (w & 1) * 32;
    const int o_mo = (w >> 1) * 16;
    const int o_no = (w & 1) * 16;
    const int s_m0 = w * 16;

    for (int ck = 0; ck < NC_; ck++) {
        const float* crow = qb + (size_t)ck * CHK_ * QKVW;
        for (int f = tid; f < 64 * 32; f += 256) {
            int r = f >> 5;
            int d4 = (f & 31) << 2;
            float4 qv = *(const float4*)(crow + (size_t)r * QKVW + d4);
            sQ[r * QS + d4 + 0] = rtf(qv.x); sQ[r * QS + d4 + 1] = rtf(qv.y);
            sQ[r * QS + d4 + 2] = rtf(qv.z); sQ[r * QS + d4 + 3] = rtf(qv.w);
            float4 kv = *(const float4*)(crow + (size_t)r * QKVW + 2048 + d4);
            sK[r * QS + d4 + 0] = rtf(kv.x); sK[r * QS + d4 + 1] = rtf(kv.y);
            sK[r * QS + d4 + 2] = rtf(kv.z); sK[r * QS + d4 + 3] = rtf(kv.w);
        }
        for (int f = tid; f < 64 * 8; f += 256) {
            int r = f >> 3;
            int d4 = (f & 7) << 2;
            float4 vv = *(const float4*)(crow + (size_t)r * QKVW + 4096 + dvb + d4);
            sV[r * VS + d4 + 0] = rtf(vv.x); sV[r * VS + d4 + 1] = rtf(vv.y);
            sV[r * VS + d4 + 2] = rtf(vv.z); sV[r * VS + d4 + 3] = rtf(vv.w);
        }
        __syncthreads();

        // ---- att = Q @ K^T (64x64, k=128), mask+decay -> sAtt (rounded) ----
        {
            float fa[4][4];
#pragma unroll
            for (int nt = 0; nt < 4; nt++)
#pragma unroll
                for (int i = 0; i < 4; i++) fa[nt][i] = 0.f;
#pragma unroll
            for (int k0 = 0; k0 < 16; k0++) {
                uint32_t a[4];
                const float* pa = sQ + (a_mq + g) * QS + k0 * 8 + c;
                a[0] = __float_as_uint(pa[0]);
                a[1] = __float_as_uint(pa[8 * QS]);
                a[2] = __float_as_uint(pa[4]);
                a[3] = __float_as_uint(pa[8 * QS + 4]);
#pragma unroll
                for (int nt = 0; nt < 4; nt++) {
                    uint32_t bb[2];
                    const float* pb = sK + (a_ne + nt * 8 + g) * QS + k0 * 8 + c;
                    bb[0] = __float_as_uint(pb[0]);
                    bb[1] = __float_as_uint(pb[4]);
                    mma_tf32(fa[nt], a, bb);
                }
            }
#pragma unroll
            for (int nt = 0; nt < 4; nt++) {
                const int e0 = a_ne + nt * 8 + 2 * c;
                const int r0 = a_mq + g, r1 = a_mq + g + 8;
                float v;
                v = (r0 >= e0)     ? fa[nt][0] * expg[r0 - e0]     : 0.f;
                sAtt[r0 * AS + e0]     = rtf(v);
                v = (r0 >= e0 + 1) ? fa[nt][1] * expg[r0 - e0 - 1] : 0.f;
                sAtt[r0 * AS + e0 + 1] = rtf(v);
                v = (r1 >= e0)     ? fa[nt][2] * expg[r1 - e0]     : 0.f;
                sAtt[r1 * AS + e0]     = rtf(v);
                v = (r1 >= e0 + 1) ? fa[nt][3] * expg[r1 - e0 - 1] : 0.f;
                sAtt[r1 * AS + e0 + 1] = rtf(v);
            }
        }
        __syncthreads();

        // ---- o = att @ V + qdec * (Q @ S_prev)  (64x32) -> gmem ----
        {
            float fi[2][4], fr[2][4];
#pragma unroll
            for (int nt = 0; nt < 2; nt++)
#pragma unroll
                for (int i = 0; i < 4; i++) { fi[nt][i] = 0.f; fr[nt][i] = 0.f; }
#pragma unroll
            for (int k0 = 0; k0 < 8; k0++) {          // intra, k over e
                uint32_t a[4];
                const float* pa = sAtt + (o_mo + g) * AS + k0 * 8 + c;
                a[0] = __float_as_uint(pa[0]);
                a[1] = __float_as_uint(pa[8 * AS]);
                a[2] = __float_as_uint(pa[4]);
                a[3] = __float_as_uint(pa[8 * AS + 4]);
#pragma unroll
                for (int nt = 0; nt < 2; nt++) {
                    uint32_t bb[2];
                    bb[0] = __float_as_uint(sV[(k0 * 8 + c) * VS + o_no + nt * 8 + g]);
                    bb[1] = __float_as_uint(sV[(k0 * 8 + c + 4) * VS + o_no + nt * 8 + g]);
                    mma_tf32(fi[nt], a, bb);
                }
            }
#pragma unroll
            for (int k0 = 0; k0 < 16; k0++) {         // inter, k over d
                uint32_t a[4];
                const float* pa = sQ + (o_mo + g) * QS + k0 * 8 + c;
                a[0] = __float_as_uint(pa[0]);
                a[1] = __float_as_uint(pa[8 * QS]);
                a[2] = __float_as_uint(pa[4]);
                a[3] = __float_as_uint(pa[8 * QS + 4]);
#pragma unroll
                for (int nt = 0; nt < 2; nt++) {
                    uint32_t bb[2];
                    bb[0] = __float_as_uint(sS[(k0 * 8 + c) * VS + o_no + nt * 8 + g]);
                    bb[1] = __float_as_uint(sS[(k0 * 8 + c + 4) * VS + o_no + nt * 8 + g]);
                    mma_tf32(fr[nt], a, bb);
                }
            }
            const int r0 = o_mo + g, r1 = o_mo + g + 8;
            const float qd0 = expg[r0 + 1], qd1 = expg[r1 + 1];
            const size_t obase = ((size_t)b * T_ + (size_t)ck * CHK_) * HID_ + h * D_ + dvb;
#pragma unroll
            for (int nt = 0; nt < 2; nt++) {
                const int col = o_no + nt * 8 + 2 * c;
                *(float2*)(o_out + obase + (size_t)r0 * HID_ + col) =
                    make_float2(fi[nt][0] + qd0 * fr[nt][0], fi[nt][1] + qd0 * fr[nt][1]);
                *(float2*)(o_out + obase + (size_t)r1 * HID_ + col) =
                    make_float2(fi[nt][2] + qd1 * fr[nt][2], fi[nt][3] + qd1 * fr[nt][3]);
            }
        }

        // ---- state: fs = chdec*fs + (kdec*K)^T @ V   (128x32, k=64) ----
        {
#pragma unroll
            for (int nt = 0; nt < 4; nt++)
#pragma unroll
                for (int i = 0; i < 4; i++) fs[nt][i] *= chdec;
#pragma unroll
            for (int k0 = 0; k0 < 8; k0++) {
                const float kd0 = expg[63 - (k0 * 8 + c)];
                const float kd1 = expg[63 - (k0 * 8 + c + 4)];
                uint32_t a[4];
                a[0] = rtu(sK[(k0 * 8 + c) * QS + s_m0 + g] * kd0);
                a[1] = rtu(sK[(k0 * 8 + c) * QS + s_m0 + g + 8] * kd0);
                a[2] = rtu(sK[(k0 * 8 + c + 4) * QS + s_m0 + g] * kd1);
                a[3] = rtu(sK[(k0 * 8 + c + 4) * QS + s_m0 + g + 8] * kd1);
#pragma unroll
                for (int nt = 0; nt < 4; nt++) {
                    uint32_t bb[2];
                    bb[0] = __float_as_uint(sV[(k0 * 8 + c) * VS + nt * 8 + g]);
                    bb[1] = __float_as_uint(sV[(k0 * 8 + c + 4) * VS + nt * 8 + g]);
                    mma_tf32(fs[nt], a, bb);
                }
            }
        }
        __syncthreads();

        // mirror state frags to sS (tf32-rounded) for next chunk's q@S
        {
            const int r0 = s_m0 + g, r1 = s_m0 + g + 8;
#pragma unroll
            for (int nt = 0; nt < 4; nt++) {
                const int col = nt * 8 + 2 * c;
                sS[r0 * VS + col]     = rtf(fs[nt][0]);
                sS[r0 * VS + col + 1] = rtf(fs[nt][1]);
                sS[r1 * VS + col]     = rtf(fs[nt][2]);
                sS[r1 * VS + col + 1] = rtf(fs[nt][3]);
            }
        }
    }
}

// ---------------- group rmsnorm * sigmoid(gate); emits fp16 og ----------------
__global__ __launch_bounds__(256)
void epilogue_k(const float* __restrict__ o_in, const float* __restrict__ gate,
                const float* __restrict__ gw, __half* __restrict__ og) {
    const int bt = blockIdx.x;
    const int lane = threadIdx.x & 31;
    const int warp = threadIdx.x >> 5;
    for (int hh = warp; hh < H_; hh += 8) {
        const size_t base = (size_t)bt * HID_ + hh * D_;
        const float* row = o_in + base;
        float v0 = row[lane], v1 = row[lane + 32], v2 = row[lane + 64], v3 = row[lane + 96];
        float ss = v0 * v0 + v1 * v1 + v2 * v2 + v3 * v3;
#pragma unroll
        for (int o = 16; o; o >>= 1) ss += __shfl_xor_sync(0xFFFFFFFFu, ss, o);
        const float rs = rsqrtf(ss * (1.f / 128.f) + 1e-6f);
        const float* gr = gate + base;
        __half* out = og + base;
#pragma unroll
        for (int i = 0; i < 4; i++) {
            const int d = lane + 32 * i;
            float v = (i == 0) ? v0 : (i == 1) ? v1 : (i == 2) ? v2 : v3;
            float sg = 1.f / (1.f + expf(-gr[d]));
            out[d] = __float2half_rn(v * rs * gw[hh * D_ + d] * sg);
        }
    }
}

// ---------------- launch ----------------
extern "C" void kernel_launch(void* const* d_in, const int* in_sizes, int n_in,
                              void* d_out, int out_size) {
    const float* hidden   = (const float*)d_in[0];
    const float* w_qkv    = (const float*)d_in[1];
    const float* q_ln_w   = (const float*)d_in[2];
    const float* k_ln_w   = (const float*)d_in[3];
    const float* g_norm_w = (const float*)d_in[4];
    const float* w_g_proj = (const float*)d_in[5];
    const float* w_dense  = (const float*)d_in[6];
    const int*   pos_ids  = (const int*)d_in[7];
    float* out = (float*)d_out;

    float *qkv_p, *gate_p, *o_p;
    __half *og_p, *hid_p, *wqkv_p, *wg_p, *wd_p;
    cudaGetSymbolAddress((void**)&qkv_p, g_qkv);
    cudaGetSymbolAddress((void**)&gate_p, g_gate);
    cudaGetSymbolAddress((void**)&o_p, g_o);
    cudaGetSymbolAddress((void**)&og_p, g_og_h);
    cudaGetSymbolAddress((void**)&hid_p, g_hid_h);
    cudaGetSymbolAddress((void**)&wqkv_p, g_wqkv_h);
    cudaGetSymbolAddress((void**)&wg_p, g_wg_h);
    cudaGetSymbolAddress((void**)&wd_p, g_wd_h);

    const int M = B_ * T_;
    cudaFuncSetAttribute(gla_kernel, cudaFuncAttributeMaxDynamicSharedMemorySize,
                         GLA_SMEM_FLOATS * (int)sizeof(float));
    cudaFuncSetAttribute(gemm_mma, cudaFuncAttributeMaxDynamicSharedMemorySize, GSMEM);

    // 0) fp32 -> fp16 converts for GEMM operands
    {
        int n4;
        n4 = (M * HID_) / 4;
        cvt_f2h<<<(n4 + 255) / 256, 256>>>((const float4*)hidden, (uint2*)hid_p, n4);
        n4 = (QKVW * HID_) / 4;
        cvt_f2h<<<(n4 + 255) / 256, 256>>>((const float4*)w_qkv, (uint2*)wqkv_p, n4);
        n4 = (HID_ * HID_) / 4;
        cvt_f2h<<<(n4 + 255) / 256, 256>>>((const float4*)w_g_proj, (uint2*)wg_p, n4);
        cvt_f2h<<<(n4 + 255) / 256, 256>>>((const float4*)w_dense, (uint2*)wd_p, n4);
    }

    // 1) qkv projection (fp16 m16n8k16, R6 skeleton)
    gemm_mma<<<dim3(QKVW / 128, M / 128), 256, GSMEM>>>(hid_p, wqkv_p, qkv_p, M, QKVW, HID_);
    // 2) gate projection
    gemm_mma<<<dim3(HID_ / 128, M / 128), 256, GSMEM>>>(hid_p, wg_p, gate_p, M, HID_, HID_);
    // 3) rmsnorm + rope on q,k
    prep_qk<<<M, 256>>>(qkv_p, q_ln_w, k_ln_w, pos_ids);
    // 4) chunked gated linear attention (tf32, R6-proven)
    gla_kernel<<<dim3(4, H_, B_), 256, GLA_SMEM_FLOATS * sizeof(float)>>>(qkv_p, o_p);
    // 5) group rmsnorm * sigmoid gate -> fp16 og
    epilogue_k<<<M, 256>>>(o_p, gate_p, g_norm_w, og_p);
    // 6) dense output projection
    gemm_mma<<<dim3(HID_ / 128, M / 128), 256, GSMEM>>>(og_p, wd_p, out, M, HID_, HID_);
}

// round 16
// speedup vs baseline: 1.9205x; 1.0131x over previous
#include <cuda_runtime.h>
#include <cuda_fp16.h>
#include <cstdint>
#include <math.h>

#define B_   2
#define T_   4096
#define HID_ 2048
#define H_   16
#define D_   128
#define NC_  64      // T/CHUNK
#define CHK_ 64
#define QKVW 6144    // 3*H*D

// ---------------- scratch (static device globals; no runtime alloc) ----------------
__device__ float  g_qkv[(size_t)B_ * T_ * QKVW];
__device__ float  g_gate[(size_t)B_ * T_ * HID_];
__device__ float  g_o[(size_t)B_ * T_ * HID_];
__device__ __half g_og_h[(size_t)B_ * T_ * HID_];     // gated output, fp16 (GEMM3 A)
__device__ __half g_hid_h[(size_t)B_ * T_ * HID_];    // fp16 hidden
__device__ __half g_wqkv_h[(size_t)QKVW * HID_];      // fp16 weights
__device__ __half g_wg_h[(size_t)HID_ * HID_];
__device__ __half g_wd_h[(size_t)HID_ * HID_];

// ================= helpers =================
__device__ __forceinline__ uint32_t smem_u32(const void* p) {
    uint32_t a;
    asm("{ .reg .u64 t; cvta.to.shared.u64 t, %1; cvt.u32.u64 %0, t; }" : "=r"(a) : "l"(p));
    return a;
}
#define CP_ASYNC16(dst, src) \
    asm volatile("cp.async.cg.shared.global [%0], [%1], 16;" \
                 :: "r"(dst), "l"(__cvta_generic_to_global(src)))
#define CP_COMMIT() asm volatile("cp.async.commit_group;" ::: "memory")
#define CP_WAIT1()  asm volatile("cp.async.wait_group 1;" ::: "memory")

__device__ __forceinline__ void mma_f16(float* d, const uint32_t* a, const uint32_t* b) {
    asm volatile(
        "mma.sync.aligned.m16n8k16.row.col.f32.f16.f16.f32 "
        "{%0,%1,%2,%3}, {%4,%5,%6,%7}, {%8,%9}, {%0,%1,%2,%3};"
        : "+f"(d[0]), "+f"(d[1]), "+f"(d[2]), "+f"(d[3])
        : "r"(a[0]), "r"(a[1]), "r"(a[2]), "r"(a[3]), "r"(b[0]), "r"(b[1]));
}
__device__ __forceinline__ void mma_tf32(float* d, const uint32_t* a, const uint32_t* b) {
    asm volatile(
        "mma.sync.aligned.m16n8k8.row.col.f32.tf32.tf32.f32 "
        "{%0,%1,%2,%3}, {%4,%5,%6,%7}, {%8,%9}, {%0,%1,%2,%3};"
        : "+f"(d[0]), "+f"(d[1]), "+f"(d[2]), "+f"(d[3])
        : "r"(a[0]), "r"(a[1]), "r"(a[2]), "r"(a[3]), "r"(b[0]), "r"(b[1]));
}
__device__ __forceinline__ uint32_t h2pack(float lo, float hi) {
    __half2 h = __floats2half2_rn(lo, hi);
    return *reinterpret_cast<uint32_t*>(&h);
}
// tf32 round-to-nearest on fp32 bit pattern
__device__ __forceinline__ float rtf(float x) {
    return __uint_as_float(__float_as_uint(x) + 0x1000u);
}
__device__ __forceinline__ uint32_t rtu(float x) {
    return __float_as_uint(x) + 0x1000u;
}

// ---------------- fp32 -> fp16 bulk convert ----------------
__global__ __launch_bounds__(256)
void cvt_f2h(const float4* __restrict__ in, uint2* __restrict__ out, int n4) {
    int i = blockIdx.x * blockDim.x + threadIdx.x;
    if (i < n4) {
        float4 v = in[i];
        uint2 o;
        o.x = h2pack(v.x, v.y);
        o.y = h2pack(v.z, v.w);
        out[i] = o;
    }
}

// ================= fp16 mma.sync NT GEMM: C[M,N] = A[M,K] * B[N,K]^T =================
// Block tile 128x128, BK=32, 128 threads = 4 warps (2x2), warp tile 64x64 of
// m16n8k16 (halved cross-warp fragment redundancy -> crossbar 32KB/CTA-iter).
// Scalar LDS.32 fragment loads, 2-stage cp.async load-before-wait, 2 CTAs/SM.
#define HS    40                            // halves per smem row (32 + 8 pad)
#define HSTGH (256 * HS)                    // halves per stage (A 128 rows + B 128 rows)
#define GSMEM (2 * HSTGH * 2)               // bytes: 2 stages * stage * 2B = 40960

__global__ __launch_bounds__(128, 2)
void gemm_mma(const __half* __restrict__ A, const __half* __restrict__ Bm,
              float* __restrict__ C, int M, int N, int K) {
    extern __shared__ __half hsm[];
    const uint32_t sb = smem_u32(hsm);
    const int tid = threadIdx.x;
    const int lane = tid & 31, wid = tid >> 5;
    const int g = lane >> 2, c = lane & 3;
    const int bm = blockIdx.y * 128, bn = blockIdx.x * 128;
    const int wm = (wid >> 1) * 64, wn = (wid & 1) * 64;
    const int KIT = K >> 5;

    auto load_stage = [&](int s, int kt) {
        const uint32_t ab = sb + (uint32_t)s * (HSTGH * 2);
        const uint32_t bb = ab + 128 * HS * 2;
        const size_t kofs = (size_t)kt * 32;
#pragma unroll
        for (int i = 0; i < 4; i++) {              // A: 128 rows x 4 chunks of 8 halves
            int id = tid + i * 128;
            int row = id >> 2, c4 = id & 3;
            CP_ASYNC16(ab + (uint32_t)(row * (HS * 2) + c4 * 16),
                       A + (size_t)(bm + row) * K + kofs + c4 * 8);
        }
#pragma unroll
        for (int i = 0; i < 4; i++) {              // B: 128 rows x 4 chunks
            int id = tid + i * 128;
            int row = id >> 2, c4 = id & 3;
            CP_ASYNC16(bb + (uint32_t)(row * (HS * 2) + c4 * 16),
                       Bm + (size_t)(bn + row) * K + kofs + c4 * 8);
        }
    };

    float d[4][8][4];
#pragma unroll
    for (int mt = 0; mt < 4; mt++)
#pragma unroll
        for (int nt = 0; nt < 8; nt++)
#pragma unroll
            for (int i = 0; i < 4; i++) d[mt][nt][i] = 0.f;

    load_stage(0, 0);
    CP_COMMIT();

    for (int it = 0; it < KIT; it++) {
        if (it + 1 < KIT) load_stage((it + 1) & 1, it + 1);
        CP_COMMIT();
        CP_WAIT1();
        __syncthreads();

        const __half* As = hsm + (it & 1) * HSTGH;
        const __half* Bs = As + 128 * HS;
#pragma unroll
        for (int ks = 0; ks < 2; ks++) {
            const int kb = ks * 16;
            uint32_t a[4][4];
#pragma unroll
            for (int mt = 0; mt < 4; mt++) {
                const __half* p = As + (wm + mt * 16 + g) * HS + kb + 2 * c;
                a[mt][0] = *(const uint32_t*)(p);
                a[mt][1] = *(const uint32_t*)(p + 8 * HS);
                a[mt][2] = *(const uint32_t*)(p + 8);
                a[mt][3] = *(const uint32_t*)(p + 8 * HS + 8);
            }
            uint32_t b[8][2];
#pragma unroll
            for (int nt = 0; nt < 8; nt++) {
                const __half* q = Bs + (wn + nt * 8 + g) * HS + kb + 2 * c;
                b[nt][0] = *(const uint32_t*)(q);
                b[nt][1] = *(const uint32_t*)(q + 8);
            }
#pragma unroll
            for (int mt = 0; mt < 4; mt++)
#pragma unroll
                for (int nt = 0; nt < 8; nt++)
                    mma_f16(d[mt][nt], a[mt], b[nt]);
        }
        __syncthreads();
    }

#pragma unroll
    for (int mt = 0; mt < 4; mt++) {
        const int r0 = bm + wm + mt * 16 + g;
#pragma unroll
        for (int nt = 0; nt < 8; nt++) {
            const int c0 = bn + wn + nt * 8 + 2 * c;
            *(float2*)&C[(size_t)r0 * N + c0]       = make_float2(d[mt][nt][0], d[mt][nt][1]);
            *(float2*)&C[(size_t)(r0 + 8) * N + c0] = make_float2(d[mt][nt][2], d[mt][nt][3]);
        }
    }
}

// ---------------- q/k rmsnorm + RoPE (+ q * D^-0.5), in place on g_qkv ----------------
__global__ __launch_bounds__(256)
void prep_qk(float* __restrict__ qkv, const float* __restrict__ qw,
             const float* __restrict__ kw, const int* __restrict__ pos_ids) {
    const int bt = blockIdx.x;
    const int lane = threadIdx.x & 31;
    const int warp = threadIdx.x >> 5;
    const float pos = (float)pos_ids[bt];
    const float invf = expf(-(float)lane * (logf(10000.0f) / 32.0f));
    const float fr = pos * invf;
    const float cs = cosf(fr), sn = sinf(fr);

    for (int r = warp; r < 32; r += 8) {
        const int hh = r >> 1;
        const int isK = r & 1;
        float* row = qkv + (size_t)bt * QKVW + isK * (H_ * D_) + hh * D_;
        const float* w = isK ? kw : qw;
        float v0 = row[lane], v1 = row[lane + 32], v2 = row[lane + 64], v3 = row[lane + 96];
        float ss = v0 * v0 + v1 * v1 + v2 * v2 + v3 * v3;
#pragma unroll
        for (int o = 16; o; o >>= 1) ss += __shfl_xor_sync(0xFFFFFFFFu, ss, o);
        const float rs = rsqrtf(ss * (1.f / 128.f) + 1e-6f);
        v0 = v0 * rs * w[lane];      v1 = v1 * rs * w[lane + 32];
        v2 = v2 * rs * w[lane + 64]; v3 = v3 * rs * w[lane + 96];
        float nv0 = v0 * cs - v1 * sn;
        float nv1 = v1 * cs + v0 * sn;
        v0 = nv0; v1 = nv1;
        if (!isK) {
            const float sc = 0.08838834764831845f;
            v0 *= sc; v1 *= sc; v2 *= sc; v3 *= sc;
        }
        row[lane] = v0; row[lane + 32] = v1; row[lane + 64] = v2; row[lane + 96] = v3;
    }
}

// ================= chunked GLA, tf32 mma.sync, 256 threads (R6-proven) =================
#define QS 132   // sQ/sK row stride (floats)
#define VS 36    // sV/sS row stride
#define AS 68    // sAtt row stride
#define GLA_SMEM_FLOATS (64*QS + 64*QS + 64*VS + 128*VS + 64*AS + 80)

__global__ __launch_bounds__(256, 1)
void gla_kernel(const float* __restrict__ qkv, float* __restrict__ o_out) {
    extern __shared__ float sm[];
    float* sQ   = sm;                  // [64][QS]
    float* sK   = sQ + 64 * QS;        // [64][QS]
    float* sV   = sK + 64 * QS;        // [64][VS]
    float* sS   = sV + 64 * VS;        // [128][VS]
    float* sAtt = sS + 128 * VS;       // [64][AS]
    float* expg = sAtt + 64 * AS;      // [80]

    const int tid = threadIdx.x;
    const int lane = tid & 31, w = tid >> 5;
    const int g = lane >> 2, c = lane & 3;
    const int gs = blockIdx.x;
    const int h  = blockIdx.y;
    const int b  = blockIdx.z;

    float gg;
    {
        const double scale = 1.0 - 11.0 / 31.0 + 1e-5;
        const double sl = pow(2.0, -0.5 * (double)(h + 1));
        gg = (float)(-sl * scale);
    }
    if (tid <= 64) expg[tid] = expf(gg * (float)tid);
    for (int i = tid; i < 128 * VS; i += 256) sS[i] = 0.f;

    float fs[4][4];
#pragma unroll
    for (int nt = 0; nt < 4; nt++)
#pragma unroll
        for (int i = 0; i < 4; i++) fs[nt][i] = 0.f;

    __syncthreads();
    const float chdec = expg[64];

    const float* qb = qkv + (size_t)b * T_ * QKVW + h * D_;
    const int dvb = gs * 32;

    const int a_mq = (w >> 1) * 16;
    const int a_ne = (w & 1) * 32;
    const int o_mo = (w >> 1) * 16;
    const int o_no = (w & 1) * 16;
    const int s_m0 = w * 16;

    for (int ck = 0; ck < NC_; ck++) {
        const float* crow = qb + (size_t)ck * CHK_ * QKVW;
        for (int f = tid; f < 64 * 32; f += 256) {
            int r = f >> 5;
            int d4 = (f & 31) << 2;
            float4 qv = *(const float4*)(crow + (size_t)r * QKVW + d4);
            sQ[r * QS + d4 + 0] = rtf(qv.x); sQ[r * QS + d4 + 1] = rtf(qv.y);
            sQ[r * QS + d4 + 2] = rtf(qv.z); sQ[r * QS + d4 + 3] = rtf(qv.w);
            float4 kv = *(const float4*)(crow + (size_t)r * QKVW + 2048 + d4);
            sK[r * QS + d4 + 0] = rtf(kv.x); sK[r * QS + d4 + 1] = rtf(kv.y);
            sK[r * QS + d4 + 2] = rtf(kv.z); sK[r * QS + d4 + 3] = rtf(kv.w);
        }
        for (int f = tid; f < 64 * 8; f += 256) {
            int r = f >> 3;
            int d4 = (f & 7) << 2;
            float4 vv = *(const float4*)(crow + (size_t)r * QKVW + 4096 + dvb + d4);
            sV[r * VS + d4 + 0] = rtf(vv.x); sV[r * VS + d4 + 1] = rtf(vv.y);
            sV[r * VS + d4 + 2] = rtf(vv.z); sV[r * VS + d4 + 3] = rtf(vv.w);
        }
        __syncthreads();

        // ---- att = Q @ K^T (64x64, k=128), mask+decay -> sAtt (rounded) ----
        {
            float fa[4][4];
#pragma unroll
            for (int nt = 0; nt < 4; nt++)
#pragma unroll
                for (int i = 0; i < 4; i++) fa[nt][i] = 0.f;
#pragma unroll
            for (int k0 = 0; k0 < 16; k0++) {
                uint32_t a[4];
                const float* pa = sQ + (a_mq + g) * QS + k0 * 8 + c;
                a[0] = __float_as_uint(pa[0]);
                a[1] = __float_as_uint(pa[8 * QS]);
                a[2] = __float_as_uint(pa[4]);
                a[3] = __float_as_uint(pa[8 * QS + 4]);
#pragma unroll
                for (int nt = 0; nt < 4; nt++) {
                    uint32_t bb[2];
                    const float* pb = sK + (a_ne + nt * 8 + g) * QS + k0 * 8 + c;
                    bb[0] = __float_as_uint(pb[0]);
                    bb[1] = __float_as_uint(pb[4]);
                    mma_tf32(fa[nt], a, bb);
                }
            }
#pragma unroll
            for (int nt = 0; nt < 4; nt++) {
                const int e0 = a_ne + nt * 8 + 2 * c;
                const int r0 = a_mq + g, r1 = a_mq + g + 8;
                float v;
                v = (r0 >= e0)     ? fa[nt][0] * expg[r0 - e0]     : 0.f;
                sAtt[r0 * AS + e0]     = rtf(v);
                v = (r0 >= e0 + 1) ? fa[nt][1] * expg[r0 - e0 - 1] : 0.f;
                sAtt[r0 * AS + e0 + 1] = rtf(v);
                v = (r1 >= e0)     ? fa[nt][2] * expg[r1 - e0]     : 0.f;
                sAtt[r1 * AS + e0]     = rtf(v);
                v = (r1 >= e0 + 1) ? fa[nt][3] * expg[r1 - e0 - 1] : 0.f;
                sAtt[r1 * AS + e0 + 1] = rtf(v);
            }
        }
        __syncthreads();

        // ---- o = att @ V + qdec * (Q @ S_prev)  (64x32) -> gmem ----
        {
            float fi[2][4], fr[2][4];
#pragma unroll
            for (int nt = 0; nt < 2; nt++)
#pragma unroll
                for (int i = 0; i < 4; i++) { fi[nt][i] = 0.f; fr[nt][i] = 0.f; }
#pragma unroll
            for (int k0 = 0; k0 < 8; k0++) {          // intra, k over e
                uint32_t a[4];
                const float* pa = sAtt + (o_mo + g) * AS + k0 * 8 + c;
                a[0] = __float_as_uint(pa[0]);
                a[1] = __float_as_uint(pa[8 * AS]);
                a[2] = __float_as_uint(pa[4]);
                a[3] = __float_as_uint(pa[8 * AS + 4]);
#pragma unroll
                for (int nt = 0; nt < 2; nt++) {
                    uint32_t bb[2];
                    bb[0] = __float_as_uint(sV[(k0 * 8 + c) * VS + o_no + nt * 8 + g]);
                    bb[1] = __float_as_uint(sV[(k0 * 8 + c + 4) * VS + o_no + nt * 8 + g]);
                    mma_tf32(fi[nt], a, bb);
                }
            }
#pragma unroll
            for (int k0 = 0; k0 < 16; k0++) {         // inter, k over d
                uint32_t a[4];
                const float* pa = sQ + (o_mo + g) * QS + k0 * 8 + c;
                a[0] = __float_as_uint(pa[0]);
                a[1] = __float_as_uint(pa[8 * QS]);
                a[2] = __float_as_uint(pa[4]);
                a[3] = __float_as_uint(pa[8 * QS + 4]);
#pragma unroll
                for (int nt = 0; nt < 2; nt++) {
                    uint32_t bb[2];
                    bb[0] = __float_as_uint(sS[(k0 * 8 + c) * VS + o_no + nt * 8 + g]);
                    bb[1] = __float_as_uint(sS[(k0 * 8 + c + 4) * VS + o_no + nt * 8 + g]);
                    mma_tf32(fr[nt], a, bb);
                }
            }
            const int r0 = o_mo + g, r1 = o_mo + g + 8;
            const float qd0 = expg[r0 + 1], qd1 = expg[r1 + 1];
            const size_t obase = ((size_t)b * T_ + (size_t)ck * CHK_) * HID_ + h * D_ + dvb;
#pragma unroll
            for (int nt = 0; nt < 2; nt++) {
                const int col = o_no + nt * 8 + 2 * c;
                *(float2*)(o_out + obase + (size_t)r0 * HID_ + col) =
                    make_float2(fi[nt][0] + qd0 * fr[nt][0], fi[nt][1] + qd0 * fr[nt][1]);
                *(float2*)(o_out + obase + (size_t)r1 * HID_ + col) =
                    make_float2(fi[nt][2] + qd1 * fr[nt][2], fi[nt][3] + qd1 * fr[nt][3]);
            }
        }

        // ---- state: fs = chdec*fs + (kdec*K)^T @ V   (128x32, k=64) ----
        {
#pragma unroll
            for (int nt = 0; nt < 4; nt++)
#pragma unroll
                for (int i = 0; i < 4; i++) fs[nt][i] *= chdec;
#pragma unroll
            for (int k0 = 0; k0 < 8; k0++) {
                const float kd0 = expg[63 - (k0 * 8 + c)];
                const float kd1 = expg[63 - (k0 * 8 + c + 4)];
                uint32_t a[4];
                a[0] = rtu(sK[(k0 * 8 + c) * QS + s_m0 + g] * kd0);
                a[1] = rtu(sK[(k0 * 8 + c) * QS + s_m0 + g + 8] * kd0);
                a[2] = rtu(sK[(k0 * 8 + c + 4) * QS + s_m0 + g] * kd1);
                a[3] = rtu(sK[(k0 * 8 + c + 4) * QS + s_m0 + g + 8] * kd1);
#pragma unroll
                for (int nt = 0; nt < 4; nt++) {
                    uint32_t bb[2];
                    bb[0] = __float_as_uint(sV[(k0 * 8 + c) * VS + nt * 8 + g]);
                    bb[1] = __float_as_uint(sV[(k0 * 8 + c + 4) * VS + nt * 8 + g]);
                    mma_tf32(fs[nt], a, bb);
                }
            }
        }
        __syncthreads();

        // mirror state frags to sS (tf32-rounded) for next chunk's q@S
        {
            const int r0 = s_m0 + g, r1 = s_m0 + g + 8;
#pragma unroll
            for (int nt = 0; nt < 4; nt++) {
                const int col = nt * 8 + 2 * c;
                sS[r0 * VS + col]     = rtf(fs[nt][0]);
                sS[r0 * VS + col + 1] = rtf(fs[nt][1]);
                sS[r1 * VS + col]     = rtf(fs[nt][2]);
                sS[r1 * VS + col + 1] = rtf(fs[nt][3]);
            }
        }
    }
}

// ---------------- group rmsnorm * sigmoid(gate); emits fp16 og ----------------
__global__ __launch_bounds__(256)
void epilogue_k(const float* __restrict__ o_in, const float* __restrict__ gate,
                const float* __restrict__ gw, __half* __restrict__ og) {
    const int bt = blockIdx.x;
    const int lane = threadIdx.x & 31;
    const int warp = threadIdx.x >> 5;
    for (int hh = warp; hh < H_; hh += 8) {
        const size_t base = (size_t)bt * HID_ + hh * D_;
        const float* row = o_in + base;
        float v0 = row[lane], v1 = row[lane + 32], v2 = row[lane + 64], v3 = row[lane + 96];
        float ss = v0 * v0 + v1 * v1 + v2 * v2 + v3 * v3;
#pragma unroll
        for (int o = 16; o; o >>= 1) ss += __shfl_xor_sync(0xFFFFFFFFu, ss, o);
        const float rs = rsqrtf(ss * (1.f / 128.f) + 1e-6f);
        const float* gr = gate + base;
        __half* out = og + base;
#pragma unroll
        for (int i = 0; i < 4; i++) {
            const int d = lane + 32 * i;
            float v = (i == 0) ? v0 : (i == 1) ? v1 : (i == 2) ? v2 : v3;
            float sg = 1.f / (1.f + expf(-gr[d]));
            out[d] = __float2half_rn(v * rs * gw[hh * D_ + d] * sg);
        }
    }
}

// ---------------- launch ----------------
extern "C" void kernel_launch(void* const* d_in, const int* in_sizes, int n_in,
                              void* d_out, int out_size) {
    const float* hidden   = (const float*)d_in[0];
    const float* w_qkv    = (const float*)d_in[1];
    const float* q_ln_w   = (const float*)d_in[2];
    const float* k_ln_w   = (const float*)d_in[3];
    const float* g_norm_w = (const float*)d_in[4];
    const float* w_g_proj = (const float*)d_in[5];
    const float* w_dense  = (const float*)d_in[6];
    const int*   pos_ids  = (const int*)d_in[7];
    float* out = (float*)d_out;

    float *qkv_p, *gate_p, *o_p;
    __half *og_p, *hid_p, *wqkv_p, *wg_p, *wd_p;
    cudaGetSymbolAddress((void**)&qkv_p, g_qkv);
    cudaGetSymbolAddress((void**)&gate_p, g_gate);
    cudaGetSymbolAddress((void**)&o_p, g_o);
    cudaGetSymbolAddress((void**)&og_p, g_og_h);
    cudaGetSymbolAddress((void**)&hid_p, g_hid_h);
    cudaGetSymbolAddress((void**)&wqkv_p, g_wqkv_h);
    cudaGetSymbolAddress((void**)&wg_p, g_wg_h);
    cudaGetSymbolAddress((void**)&wd_p, g_wd_h);

    const int M = B_ * T_;
    cudaFuncSetAttribute(gla_kernel, cudaFuncAttributeMaxDynamicSharedMemorySize,
                         GLA_SMEM_FLOATS * (int)sizeof(float));
    cudaFuncSetAttribute(gemm_mma, cudaFuncAttributeMaxDynamicSharedMemorySize, GSMEM);

    // 0) fp32 -> fp16 converts for GEMM operands
    {
        int n4;
        n4 = (M * HID_) / 4;
        cvt_f2h<<<(n4 + 255) / 256, 256>>>((const float4*)hidden, (uint2*)hid_p, n4);
        n4 = (QKVW * HID_) / 4;
        cvt_f2h<<<(n4 + 255) / 256, 256>>>((const float4*)w_qkv, (uint2*)wqkv_p, n4);
        n4 = (HID_ * HID_) / 4;
        cvt_f2h<<<(n4 + 255) / 256, 256>>>((const float4*)w_g_proj, (uint2*)wg_p, n4);
        cvt_f2h<<<(n4 + 255) / 256, 256>>>((const float4*)w_dense, (uint2*)wd_p, n4);
    }

    // 1) qkv projection (fp16 m16n8k16, 4-warp 64x64 warp tiles)
    gemm_mma<<<dim3(QKVW / 128, M / 128), 128, GSMEM>>>(hid_p, wqkv_p, qkv_p, M, QKVW, HID_);
    // 2) gate projection
    gemm_mma<<<dim3(HID_ / 128, M / 128), 128, GSMEM>>>(hid_p, wg_p, gate_p, M, HID_, HID_);
    // 3) rmsnorm + rope on q,k
    prep_qk<<<M, 256>>>(qkv_p, q_ln_w, k_ln_w, pos_ids);
    // 4) chunked gated linear attention (tf32, R6-proven)
    gla_kernel<<<dim3(4, H_, B_), 256, GLA_SMEM_FLOATS * sizeof(float)>>>(qkv_p, o_p);
    // 5) group rmsnorm * sigmoid gate -> fp16 og
    epilogue_k<<<M, 256>>>(o_p, gate_p, g_norm_w, og_p);
    // 6) dense output projection
    gemm_mma<<<dim3(HID_ / 128, M / 128), 128, GSMEM>>>(og_p, wd_p, out, M, HID_, HID_);
}

// round 17
// speedup vs baseline: 2.0037x; 1.0433x over previous
#include <cuda_runtime.h>
#include <cuda_fp16.h>
#include <cstdint>
#include <math.h>

#define B_   2
#define T_   4096
#define HID_ 2048
#define H_   16
#define D_   128
#define NC_  64      // T/CHUNK
#define CHK_ 64
#define QKVW 6144    // 3*H*D

// ---------------- scratch (static device globals; no runtime alloc) ----------------
__device__ float  g_qkv[(size_t)B_ * T_ * QKVW];
__device__ float  g_gate[(size_t)B_ * T_ * HID_];
__device__ float  g_o[(size_t)B_ * T_ * HID_];
__device__ __half g_og_h[(size_t)B_ * T_ * HID_];     // gated output, fp16 (GEMM3 A)
__device__ __half g_hid_h[(size_t)B_ * T_ * HID_];    // fp16 hidden
__device__ __half g_wqkv_h[(size_t)QKVW * HID_];      // fp16 weights
__device__ __half g_wg_h[(size_t)HID_ * HID_];
__device__ __half g_wd_h[(size_t)HID_ * HID_];

// ================= helpers =================
__device__ __forceinline__ uint32_t smem_u32(const void* p) {
    uint32_t a;
    asm("{ .reg .u64 t; cvta.to.shared.u64 t, %1; cvt.u32.u64 %0, t; }" : "=r"(a) : "l"(p));
    return a;
}
#define CP_ASYNC16(dst, src) \
    asm volatile("cp.async.cg.shared.global [%0], [%1], 16;" \
                 :: "r"(dst), "l"(__cvta_generic_to_global(src)))
#define CP_COMMIT() asm volatile("cp.async.commit_group;" ::: "memory")
#define CP_WAIT2()  asm volatile("cp.async.wait_group 2;" ::: "memory")

__device__ __forceinline__ void mma_f16(float* d, const uint32_t* a, const uint32_t* b) {
    asm volatile(
        "mma.sync.aligned.m16n8k16.row.col.f32.f16.f16.f32 "
        "{%0,%1,%2,%3}, {%4,%5,%6,%7}, {%8,%9}, {%0,%1,%2,%3};"
        : "+f"(d[0]), "+f"(d[1]), "+f"(d[2]), "+f"(d[3])
        : "r"(a[0]), "r"(a[1]), "r"(a[2]), "r"(a[3]), "r"(b[0]), "r"(b[1]));
}
__device__ __forceinline__ void mma_tf32(float* d, const uint32_t* a, const uint32_t* b) {
    asm volatile(
        "mma.sync.aligned.m16n8k8.row.col.f32.tf32.tf32.f32 "
        "{%0,%1,%2,%3}, {%4,%5,%6,%7}, {%8,%9}, {%0,%1,%2,%3};"
        : "+f"(d[0]), "+f"(d[1]), "+f"(d[2]), "+f"(d[3])
        : "r"(a[0]), "r"(a[1]), "r"(a[2]), "r"(a[3]), "r"(b[0]), "r"(b[1]));
}
__device__ __forceinline__ uint32_t h2pack(float lo, float hi) {
    __half2 h = __floats2half2_rn(lo, hi);
    return *reinterpret_cast<uint32_t*>(&h);
}
// tf32 round-to-nearest on fp32 bit pattern
__device__ __forceinline__ float rtf(float x) {
    return __uint_as_float(__float_as_uint(x) + 0x1000u);
}
__device__ __forceinline__ uint32_t rtu(float x) {
    return __float_as_uint(x) + 0x1000u;
}

// ---------------- fp32 -> fp16 bulk convert ----------------
__global__ __launch_bounds__(256)
void cvt_f2h(const float4* __restrict__ in, uint2* __restrict__ out, int n4) {
    int i = blockIdx.x * blockDim.x + threadIdx.x;
    if (i < n4) {
        float4 v = in[i];
        uint2 o;
        o.x = h2pack(v.x, v.y);
        o.y = h2pack(v.z, v.w);
        out[i] = o;
    }
}

// ================= fp16 mma.sync NT GEMM: C[M,N] = A[M,K] * B[N,K]^T =================
// Block tile 128x128, BK=32, 128 threads = 4 warps (2x2), warp tile 64x64 of
// m16n8k16. Scalar LDS.32 fragment loads, 3-stage cp.async (commit every iter
// so stage `it` lives in group g_it; wait_group 2 == stage resident), 2 CTAs/SM.
#define HS    40                            // halves per smem row (32 + 8 pad)
#define HSTGH (256 * HS)                    // halves per stage (A 128 rows + B 128 rows)
#define GSMEM (3 * HSTGH * 2)               // bytes: 3 stages * stage * 2B = 61440

__global__ __launch_bounds__(128, 2)
void gemm_mma(const __half* __restrict__ A, const __half* __restrict__ Bm,
              float* __restrict__ C, int M, int N, int K) {
    extern __shared__ __half hsm[];
    const uint32_t sb = smem_u32(hsm);
    const int tid = threadIdx.x;
    const int lane = tid & 31, wid = tid >> 5;
    const int g = lane >> 2, c = lane & 3;
    const int bm = blockIdx.y * 128, bn = blockIdx.x * 128;
    const int wm = (wid >> 1) * 64, wn = (wid & 1) * 64;
    const int KIT = K >> 5;

    auto load_stage = [&](int s, int kt) {
        const uint32_t ab = sb + (uint32_t)s * (HSTGH * 2);
        const uint32_t bb = ab + 128 * HS * 2;
        const size_t kofs = (size_t)kt * 32;
#pragma unroll
        for (int i = 0; i < 4; i++) {              // A: 128 rows x 4 chunks of 8 halves
            int id = tid + i * 128;
            int row = id >> 2, c4 = id & 3;
            CP_ASYNC16(ab + (uint32_t)(row * (HS * 2) + c4 * 16),
                       A + (size_t)(bm + row) * K + kofs + c4 * 8);
        }
#pragma unroll
        for (int i = 0; i < 4; i++) {              // B: 128 rows x 4 chunks
            int id = tid + i * 128;
            int row = id >> 2, c4 = id & 3;
            CP_ASYNC16(bb + (uint32_t)(row * (HS * 2) + c4 * 16),
                       Bm + (size_t)(bn + row) * K + kofs + c4 * 8);
        }
    };

    float d[4][8][4];
#pragma unroll
    for (int mt = 0; mt < 4; mt++)
#pragma unroll
        for (int nt = 0; nt < 8; nt++)
#pragma unroll
            for (int i = 0; i < 4; i++) d[mt][nt][i] = 0.f;

    load_stage(0, 0); CP_COMMIT();   // group g_0 = stage 0
    load_stage(1, 1); CP_COMMIT();   // group g_1 = stage 1

    for (int it = 0; it < KIT; it++) {
        if (it + 2 < KIT) load_stage((it + 2) % 3, it + 2);
        CP_COMMIT();                 // group g_{it+2} (possibly empty in tail)
        CP_WAIT2();                  // all groups <= g_it done -> stage it resident
        __syncthreads();

        const __half* As = hsm + (it % 3) * HSTGH;
        const __half* Bs = As + 128 * HS;
#pragma unroll
        for (int ks = 0; ks < 2; ks++) {
            const int kb = ks * 16;
            uint32_t a[4][4];
#pragma unroll
            for (int mt = 0; mt < 4; mt++) {
                const __half* p = As + (wm + mt * 16 + g) * HS + kb + 2 * c;
                a[mt][0] = *(const uint32_t*)(p);
                a[mt][1] = *(const uint32_t*)(p + 8 * HS);
                a[mt][2] = *(const uint32_t*)(p + 8);
                a[mt][3] = *(const uint32_t*)(p + 8 * HS + 8);
            }
            uint32_t b[8][2];
#pragma unroll
            for (int nt = 0; nt < 8; nt++) {
                const __half* q = Bs + (wn + nt * 8 + g) * HS + kb + 2 * c;
                b[nt][0] = *(const uint32_t*)(q);
                b[nt][1] = *(const uint32_t*)(q + 8);
            }
#pragma unroll
            for (int mt = 0; mt < 4; mt++)
#pragma unroll
                for (int nt = 0; nt < 8; nt++)
                    mma_f16(d[mt][nt], a[mt], b[nt]);
        }
        __syncthreads();   // protect stage (it+3)%3 == it%3 from next iter's load
    }

#pragma unroll
    for (int mt = 0; mt < 4; mt++) {
        const int r0 = bm + wm + mt * 16 + g;
#pragma unroll
        for (int nt = 0; nt < 8; nt++) {
            const int c0 = bn + wn + nt * 8 + 2 * c;
            *(float2*)&C[(size_t)r0 * N + c0]       = make_float2(d[mt][nt][0], d[mt][nt][1]);
            *(float2*)&C[(size_t)(r0 + 8) * N + c0] = make_float2(d[mt][nt][2], d[mt][nt][3]);
        }
    }
}

// ---------------- q/k rmsnorm + RoPE (+ q * D^-0.5), in place on g_qkv ----------------
__global__ __launch_bounds__(256)
void prep_qk(float* __restrict__ qkv, const float* __restrict__ qw,
             const float* __restrict__ kw, const int* __restrict__ pos_ids) {
    const int bt = blockIdx.x;
    const int lane = threadIdx.x & 31;
    const int warp = threadIdx.x >> 5;
    const float pos = (float)pos_ids[bt];
    const float invf = expf(-(float)lane * (logf(10000.0f) / 32.0f));
    const float fr = pos * invf;
    const float cs = cosf(fr), sn = sinf(fr);

    for (int r = warp; r < 32; r += 8) {
        const int hh = r >> 1;
        const int isK = r & 1;
        float* row = qkv + (size_t)bt * QKVW + isK * (H_ * D_) + hh * D_;
        const float* w = isK ? kw : qw;
        float v0 = row[lane], v1 = row[lane + 32], v2 = row[lane + 64], v3 = row[lane + 96];
        float ss = v0 * v0 + v1 * v1 + v2 * v2 + v3 * v3;
#pragma unroll
        for (int o = 16; o; o >>= 1) ss += __shfl_xor_sync(0xFFFFFFFFu, ss, o);
        const float rs = rsqrtf(ss * (1.f / 128.f) + 1e-6f);
        v0 = v0 * rs * w[lane];      v1 = v1 * rs * w[lane + 32];
        v2 = v2 * rs * w[lane + 64]; v3 = v3 * rs * w[lane + 96];
        float nv0 = v0 * cs - v1 * sn;
        float nv1 = v1 * cs + v0 * sn;
        v0 = nv0; v1 = nv1;
        if (!isK) {
            const float sc = 0.08838834764831845f;
            v0 *= sc; v1 *= sc; v2 *= sc; v3 *= sc;
        }
        row[lane] = v0; row[lane + 32] = v1; row[lane + 64] = v2; row[lane + 96] = v3;
    }
}

// ================= chunked GLA, tf32 mma.sync, 256 threads (R6-proven) =================
#define QS 132   // sQ/sK row stride (floats)
#define VS 36    // sV/sS row stride
#define AS 68    // sAtt row stride
#define GLA_SMEM_FLOATS (64*QS + 64*QS + 64*VS + 128*VS + 64*AS + 80)

__global__ __launch_bounds__(256, 1)
void gla_kernel(const float* __restrict__ qkv, float* __restrict__ o_out) {
    extern __shared__ float sm[];
    float* sQ   = sm;                  // [64][QS]
    float* sK   = sQ + 64 * QS;        // [64][QS]
    float* sV   = sK + 64 * QS;        // [64][VS]
    float* sS   = sV + 64 * VS;        // [128][VS]
    float* sAtt = sS + 128 * VS;       // [64][AS]
    float* expg = sAtt + 64 * AS;      // [80]

    const int tid = threadIdx.x;
    const int lane = tid & 31, w = tid >> 5;
    const int g = lane >> 2, c = lane & 3;
    const int gs = blockIdx.x;
    const int h  = blockIdx.y;
    const int b  = blockIdx.z;

    float gg;
    {
        const double scale = 1.0 - 11.0 / 31.0 + 1e-5;
        const double sl = pow(2.0, -0.5 * (double)(h + 1));
        gg = (float)(-sl * scale);
    }
    if (tid <= 64) expg[tid] = expf(gg * (float)tid);
    for (int i = tid; i < 128 * VS; i += 256) sS[i] = 0.f;

    float fs[4][4];
#pragma unroll
    for (int nt = 0; nt < 4; nt++)
#pragma unroll
        for (int i = 0; i < 4; i++) fs[nt][i] = 0.f;

    __syncthreads();
    const float chdec = expg[64];

    const float* qb = qkv + (size_t)b * T_ * QKVW + h * D_;
    const int dvb = gs * 32;

    const int a_mq = (w >> 1) * 16;
    const int a_ne = (w & 1) * 32;
    const int o_mo = (w >> 1) * 16;
    const int o_no = (w & 1) * 16;
    const int s_m0 = w * 16;

    for (int ck = 0; ck < NC_; ck++) {
        const float* crow = qb + (size_t)ck * CHK_ * QKVW;
        for (int f = tid; f < 64 * 32; f += 256) {
            int r = f >> 5;
            int d4 = (f & 31) << 2;
            float4 qv = *(const float4*)(crow + (size_t)r * QKVW + d4);
            sQ[r * QS + d4 + 0] = rtf(qv.x); sQ[r * QS + d4 + 1] = rtf(qv.y);
            sQ[r * QS + d4 + 2] = rtf(qv.z); sQ[r * QS + d4 + 3] = rtf(qv.w);
            float4 kv = *(const float4*)(crow + (size_t)r * QKVW + 2048 + d4);
            sK[r * QS + d4 + 0] = rtf(kv.x); sK[r * QS + d4 + 1] = rtf(kv.y);
            sK[r * QS + d4 + 2] = rtf(kv.z); sK[r * QS + d4 + 3] = rtf(kv.w);
        }
        for (int f = tid; f < 64 * 8; f += 256) {
            int r = f >> 3;
            int d4 = (f & 7) << 2;
            float4 vv = *(const float4*)(crow + (size_t)r * QKVW + 4096 + dvb + d4);
            sV[r * VS + d4 + 0] = rtf(vv.x); sV[r * VS + d4 + 1] = rtf(vv.y);
            sV[r * VS + d4 + 2] = rtf(vv.z); sV[r * VS + d4 + 3] = rtf(vv.w);
        }
        __syncthreads();

        // ---- att = Q @ K^T (64x64, k=128), mask+decay -> sAtt (rounded) ----
        {
            float fa[4][4];
#pragma unroll
            for (int nt = 0; nt < 4; nt++)
#pragma unroll
                for (int i = 0; i < 4; i++) fa[nt][i] = 0.f;
#pragma unroll
            for (int k0 = 0; k0 < 16; k0++) {
                uint32_t a[4];
                const float* pa = sQ + (a_mq + g) * QS + k0 * 8 + c;
                a[0] = __float_as_uint(pa[0]);
                a[1] = __float_as_uint(pa[8 * QS]);
                a[2] = __float_as_uint(pa[4]);
                a[3] = __float_as_uint(pa[8 * QS + 4]);
#pragma unroll
                for (int nt = 0; nt < 4; nt++) {
                    uint32_t bb[2];
                    const float* pb = sK + (a_ne + nt * 8 + g) * QS + k0 * 8 + c;
                    bb[0] = __float_as_uint(pb[0]);
                    bb[1] = __float_as_uint(pb[4]);
                    mma_tf32(fa[nt], a, bb);
                }
            }
#pragma unroll
            for (int nt = 0; nt < 4; nt++) {
                const int e0 = a_ne + nt * 8 + 2 * c;
                const int r0 = a_mq + g, r1 = a_mq + g + 8;
                float v;
                v = (r0 >= e0)     ? fa[nt][0] * expg[r0 - e0]     : 0.f;
                sAtt[r0 * AS + e0]     = rtf(v);
                v = (r0 >= e0 + 1) ? fa[nt][1] * expg[r0 - e0 - 1] : 0.f;
                sAtt[r0 * AS + e0 + 1] = rtf(v);
                v = (r1 >= e0)     ? fa[nt][2] * expg[r1 - e0]     : 0.f;
                sAtt[r1 * AS + e0]     = rtf(v);
                v = (r1 >= e0 + 1) ? fa[nt][3] * expg[r1 - e0 - 1] : 0.f;
                sAtt[r1 * AS + e0 + 1] = rtf(v);
            }
        }
        __syncthreads();

        // ---- o = att @ V + qdec * (Q @ S_prev)  (64x32) -> gmem ----
        {
            float fi[2][4], fr[2][4];
#pragma unroll
            for (int nt = 0; nt < 2; nt++)
#pragma unroll
                for (int i = 0; i < 4; i++) { fi[nt][i] = 0.f; fr[nt][i] = 0.f; }
#pragma unroll
            for (int k0 = 0; k0 < 8; k0++) {          // intra, k over e
                uint32_t a[4];
                const float* pa = sAtt + (o_mo + g) * AS + k0 * 8 + c;
                a[0] = __float_as_uint(pa[0]);
                a[1] = __float_as_uint(pa[8 * AS]);
                a[2] = __float_as_uint(pa[4]);
                a[3] = __float_as_uint(pa[8 * AS + 4]);
#pragma unroll
                for (int nt = 0; nt < 2; nt++) {
                    uint32_t bb[2];
                    bb[0] = __float_as_uint(sV[(k0 * 8 + c) * VS + o_no + nt * 8 + g]);
                    bb[1] = __float_as_uint(sV[(k0 * 8 + c + 4) * VS + o_no + nt * 8 + g]);
                    mma_tf32(fi[nt], a, bb);
                }
            }
#pragma unroll
            for (int k0 = 0; k0 < 16; k0++) {         // inter, k over d
                uint32_t a[4];
                const float* pa = sQ + (o_mo + g) * QS + k0 * 8 + c;
                a[0] = __float_as_uint(pa[0]);
                a[1] = __float_as_uint(pa[8 * QS]);
                a[2] = __float_as_uint(pa[4]);
                a[3] = __float_as_uint(pa[8 * QS + 4]);
#pragma unroll
                for (int nt = 0; nt < 2; nt++) {
                    uint32_t bb[2];
                    bb[0] = __float_as_uint(sS[(k0 * 8 + c) * VS + o_no + nt * 8 + g]);
                    bb[1] = __float_as_uint(sS[(k0 * 8 + c + 4) * VS + o_no + nt * 8 + g]);
                    mma_tf32(fr[nt], a, bb);
                }
            }
            const int r0 = o_mo + g, r1 = o_mo + g + 8;
            const float qd0 = expg[r0 + 1], qd1 = expg[r1 + 1];
            const size_t obase = ((size_t)b * T_ + (size_t)ck * CHK_) * HID_ + h * D_ + dvb;
#pragma unroll
            for (int nt = 0; nt < 2; nt++) {
                const int col = o_no + nt * 8 + 2 * c;
                *(float2*)(o_out + obase + (size_t)r0 * HID_ + col) =
                    make_float2(fi[nt][0] + qd0 * fr[nt][0], fi[nt][1] + qd0 * fr[nt][1]);
                *(float2*)(o_out + obase + (size_t)r1 * HID_ + col) =
                    make_float2(fi[nt][2] + qd1 * fr[nt][2], fi[nt][3] + qd1 * fr[nt][3]);
            }
        }

        // ---- state: fs = chdec*fs + (kdec*K)^T @ V   (128x32, k=64) ----
        {
#pragma unroll
            for (int nt = 0; nt < 4; nt++)
#pragma unroll
                for (int i = 0; i < 4; i++) fs[nt][i] *= chdec;
#pragma unroll
            for (int k0 = 0; k0 < 8; k0++) {
                const float kd0 = expg[63 - (k0 * 8 + c)];
                const float kd1 = expg[63 - (k0 * 8 + c + 4)];
                uint32_t a[4];
                a[0] = rtu(sK[(k0 * 8 + c) * QS + s_m0 + g] * kd0);
                a[1] = rtu(sK[(k0 * 8 + c) * QS + s_m0 + g + 8] * kd0);
                a[2] = rtu(sK[(k0 * 8 + c + 4) * QS + s_m0 + g] * kd1);
                a[3] = rtu(sK[(k0 * 8 + c + 4) * QS + s_m0 + g + 8] * kd1);
#pragma unroll
                for (int nt = 0; nt < 4; nt++) {
                    uint32_t bb[2];
                    bb[0] = __float_as_uint(sV[(k0 * 8 + c) * VS + nt * 8 + g]);
                    bb[1] = __float_as_uint(sV[(k0 * 8 + c + 4) * VS + nt * 8 + g]);
                    mma_tf32(fs[nt], a, bb);
                }
            }
        }
        __syncthreads();

        // mirror state frags to sS (tf32-rounded) for next chunk's q@S
        {
            const int r0 = s_m0 + g, r1 = s_m0 + g + 8;
#pragma unroll
            for (int nt = 0; nt < 4; nt++) {
                const int col = nt * 8 + 2 * c;
                sS[r0 * VS + col]     = rtf(fs[nt][0]);
                sS[r0 * VS + col + 1] = rtf(fs[nt][1]);
                sS[r1 * VS + col]     = rtf(fs[nt][2]);
                sS[r1 * VS + col + 1] = rtf(fs[nt][3]);
            }
        }
    }
}

// ---------------- group rmsnorm * sigmoid(gate); emits fp16 og ----------------
__global__ __launch_bounds__(256)
void epilogue_k(const float* __restrict__ o_in, const float* __restrict__ gate,
                const float* __restrict__ gw, __half* __restrict__ og) {
    const int bt = blockIdx.x;
    const int lane = threadIdx.x & 31;
    const int warp = threadIdx.x >> 5;
    for (int hh = warp; hh < H_; hh += 8) {
        const size_t base = (size_t)bt * HID_ + hh * D_;
        const float* row = o_in + base;
        float v0 = row[lane], v1 = row[lane + 32], v2 = row[lane + 64], v3 = row[lane + 96];
        float ss = v0 * v0 + v1 * v1 + v2 * v2 + v3 * v3;
#pragma unroll
        for (int o = 16; o; o >>= 1) ss += __shfl_xor_sync(0xFFFFFFFFu, ss, o);
        const float rs = rsqrtf(ss * (1.f / 128.f) + 1e-6f);
        const float* gr = gate + base;
        __half* out = og + base;
#pragma unroll
        for (int i = 0; i < 4; i++) {
            const int d = lane + 32 * i;
            float v = (i == 0) ? v0 : (i == 1) ? v1 : (i == 2) ? v2 : v3;
            float sg = 1.f / (1.f + expf(-gr[d]));
            out[d] = __float2half_rn(v * rs * gw[hh * D_ + d] * sg);
        }
    }
}

// ---------------- launch ----------------
extern "C" void kernel_launch(void* const* d_in, const int* in_sizes, int n_in,
                              void* d_out, int out_size) {
    const float* hidden   = (const float*)d_in[0];
    const float* w_qkv    = (const float*)d_in[1];
    const float* q_ln_w   = (const float*)d_in[2];
    const float* k_ln_w   = (const float*)d_in[3];
    const float* g_norm_w = (const float*)d_in[4];
    const float* w_g_proj = (const float*)d_in[5];
    const float* w_dense  = (const float*)d_in[6];
    const int*   pos_ids  = (const int*)d_in[7];
    float* out = (float*)d_out;

    float *qkv_p, *gate_p, *o_p;
    __half *og_p, *hid_p, *wqkv_p, *wg_p, *wd_p;
    cudaGetSymbolAddress((void**)&qkv_p, g_qkv);
    cudaGetSymbolAddress((void**)&gate_p, g_gate);
    cudaGetSymbolAddress((void**)&o_p, g_o);
    cudaGetSymbolAddress((void**)&og_p, g_og_h);
    cudaGetSymbolAddress((void**)&hid_p, g_hid_h);
    cudaGetSymbolAddress((void**)&wqkv_p, g_wqkv_h);
    cudaGetSymbolAddress((void**)&wg_p, g_wg_h);
    cudaGetSymbolAddress((void**)&wd_p, g_wd_h);

    const int M = B_ * T_;
    cudaFuncSetAttribute(gla_kernel, cudaFuncAttributeMaxDynamicSharedMemorySize,
                         GLA_SMEM_FLOATS * (int)sizeof(float));
    cudaFuncSetAttribute(gemm_mma, cudaFuncAttributeMaxDynamicSharedMemorySize, GSMEM);

    // 0) fp32 -> fp16 converts for GEMM operands
    {
        int n4;
        n4 = (M * HID_) / 4;
        cvt_f2h<<<(n4 + 255) / 256, 256>>>((const float4*)hidden, (uint2*)hid_p, n4);
        n4 = (QKVW * HID_) / 4;
        cvt_f2h<<<(n4 + 255) / 256, 256>>>((const float4*)w_qkv, (uint2*)wqkv_p, n4);
        n4 = (HID_ * HID_) / 4;
        cvt_f2h<<<(n4 + 255) / 256, 256>>>((const float4*)w_g_proj, (uint2*)wg_p, n4);
        cvt_f2h<<<(n4 + 255) / 256, 256>>>((const float4*)w_dense, (uint2*)wd_p, n4);
    }

    // 1) qkv projection (fp16 m16n8k16, 3-stage pipeline)
    gemm_mma<<<dim3(QKVW / 128, M / 128), 128, GSMEM>>>(hid_p, wqkv_p, qkv_p, M, QKVW, HID_);
    // 2) gate projection
    gemm_mma<<<dim3(HID_ / 128, M / 128), 128, GSMEM>>>(hid_p, wg_p, gate_p, M, HID_, HID_);
    // 3) rmsnorm + rope on q,k
    prep_qk<<<M, 256>>>(qkv_p, q_ln_w, k_ln_w, pos_ids);
    // 4) chunked gated linear attention (tf32, R6-proven)
    gla_kernel<<<dim3(4, H_, B_), 256, GLA_SMEM_FLOATS * sizeof(float)>>>(qkv_p, o_p);
    // 5) group rmsnorm * sigmoid gate -> fp16 og
    epilogue_k<<<M, 256>>>(o_p, gate_p, g_norm_w, og_p);
    // 6) dense output projection
    gemm_mma<<<dim3(HID_ / 128, M / 128), 128, GSMEM>>>(og_p, wd_p, out, M, HID_, HID_);
}